// round 5
// baseline (speedup 1.0000x reference)
#include <cuda_runtime.h>
#include <cuda_bf16.h>
#include <math.h>
#include <stdint.h>

#define N_NODES 50000
#define N_PAD   50048            // 391 * 128
#define N_EDGES 800000
#define N_BATCH 128
#define D_IN    15
#define D_HID   256
#define D_OUT   128
#define LN_EPS  1e-5f
#define NB_SCAN 49               // ceil(50000/1024)

// ---------------- device scratch -------------------------------------------
// Activation buffers: row = 1024 bf16 = [mean_hi(0:256) | x_hi(256:512) | mean_lo(512:768) | x_lo(768:1024)]
__device__ __nv_bfloat16 g_AbfA[(size_t)N_PAD * 1024];  // 102 MB
__device__ __nv_bfloat16 g_AbfB[(size_t)N_PAD * 1024];  // 102 MB
__device__ __nv_bfloat16 g_WtAll[(256 + 256 + 128) * 1024]; // W^T bf16 hi/lo, layers 2,3,4
__device__ float g_xc1[N_PAD * 32];                   // layer-1 concat (K=32)
__device__ float g_W1[32 * D_HID];                    // layer-1 fp32 combined W
__device__ int   g_ssrc[N_EDGES];
__device__ int   g_off [N_NODES + 1];
__device__ int   g_cur [N_NODES];
__device__ int   g_deg [N_NODES];
__device__ int   g_bsum[64];
__device__ int   g_bcnt[N_BATCH];

// ---------------- PTX helpers ----------------------------------------------
__device__ __forceinline__ uint32_t smem_to_u32(const void* p) {
    uint32_t a;
    asm("{ .reg .u64 t; cvta.to.shared.u64 t, %1; cvt.u32.u64 %0, t; }" : "=r"(a) : "l"(p));
    return a;
}
#define CP16(dst, src) \
    asm volatile("cp.async.cg.shared.global [%0], [%1], 16;" :: "r"((uint32_t)(dst)), "l"(src) : "memory")
#define CP_COMMIT() asm volatile("cp.async.commit_group;" ::: "memory")
#define CP_WAIT(n)  asm volatile("cp.async.wait_group %0;" :: "n"(n) : "memory")
#define SWZ(b) ((b) ^ (((b) >> 3) & 0x70))
#define LDSM_X4(r0, r1, r2, r3, addr) \
    asm volatile("ldmatrix.sync.aligned.m8n8.x4.shared.b16 {%0,%1,%2,%3}, [%4];" \
                 : "=r"(r0), "=r"(r1), "=r"(r2), "=r"(r3) : "r"(addr))
#define MMA_BF16(d, a, b0, b1) \
    asm volatile("mma.sync.aligned.m16n8k16.row.col.f32.bf16.bf16.f32 " \
                 "{%0,%1,%2,%3}, {%4,%5,%6,%7}, {%8,%9}, {%0,%1,%2,%3};" \
                 : "+f"((d)[0]), "+f"((d)[1]), "+f"((d)[2]), "+f"((d)[3]) \
                 : "r"((a)[0]), "r"((a)[1]), "r"((a)[2]), "r"((a)[3]), \
                   "r"(b0), "r"(b1))

// ---------------- setup kernels --------------------------------------------
__global__ void k_zero(float* out) {
    int i = blockIdx.x * blockDim.x + threadIdx.x;
    if (i < N_NODES) g_deg[i] = 0;
    if (i < N_BATCH) g_bcnt[i] = 0;
    if (i < N_BATCH * D_OUT) out[i] = 0.f;
}
__global__ void k_hist_deg(const int* __restrict__ dst) {
    int e = blockIdx.x * blockDim.x + threadIdx.x;
    if (e < N_EDGES) atomicAdd(&g_deg[dst[e]], 1);
}
__global__ void k_hist_batch(const int* __restrict__ batch) {
    int n = blockIdx.x * blockDim.x + threadIdx.x;
    if (n < N_NODES) atomicAdd(&g_bcnt[batch[n]], 1);
}
__global__ void k_scanA() {
    __shared__ int ws[32];
    int tid = threadIdx.x, lane = tid & 31, wid = tid >> 5;
    int i = blockIdx.x * 1024 + tid;
    int v = (i < N_NODES) ? g_deg[i] : 0;
    int x = v;
    #pragma unroll
    for (int o = 1; o < 32; o <<= 1) {
        int t = __shfl_up_sync(0xffffffffu, x, o);
        if (lane >= o) x += t;
    }
    if (lane == 31) ws[wid] = x;
    __syncthreads();
    if (wid == 0) {
        int y = ws[lane];
        #pragma unroll
        for (int o = 1; o < 32; o <<= 1) {
            int t = __shfl_up_sync(0xffffffffu, y, o);
            if (lane >= o) y += t;
        }
        ws[lane] = y;
    }
    __syncthreads();
    int incl = x + (wid ? ws[wid - 1] : 0);
    if (i < N_NODES) g_off[i] = incl - v;
    if (tid == 1023) g_bsum[blockIdx.x] = incl;
}
__global__ void k_scanB() {
    __shared__ int s[64];
    int tid = threadIdx.x;
    s[tid] = (tid < NB_SCAN) ? g_bsum[tid] : 0;
    __syncthreads();
    if (tid == 0) {
        int acc = 0;
        for (int i = 0; i < NB_SCAN; i++) { int t = s[i]; s[i] = acc; acc += t; }
        g_off[N_NODES] = acc;
    }
    __syncthreads();
    if (tid < NB_SCAN) g_bsum[tid] = s[tid];
}
__global__ void k_scanC() {
    int i = blockIdx.x * 1024 + threadIdx.x;
    if (i < N_NODES) {
        int o = g_off[i] + g_bsum[blockIdx.x];
        g_off[i] = o;
        g_cur[i] = o;
    }
}
__global__ void k_scatter(const int* __restrict__ src, const int* __restrict__ dst) {
    int e = blockIdx.x * blockDim.x + threadIdx.x;
    if (e < N_EDGES) {
        int p = atomicAdd(&g_cur[dst[e]], 1);
        g_ssrc[p] = src[e];
    }
}

// layer-1 combined weight (fp32): rows [0,15)=Wl1, [15,30)=Wr1, [30,32)=0
__global__ void k_buildW1(const float* __restrict__ Wl, const float* __restrict__ Wr) {
    int idx = blockIdx.x * blockDim.x + threadIdx.x;
    if (idx >= 32 * D_HID) return;
    int k = idx / D_HID, n = idx - k * D_HID;
    float v = 0.f;
    if (k < D_IN)          v = Wl[k * D_HID + n];
    else if (k < 2 * D_IN) v = Wr[(k - D_IN) * D_HID + n];
    g_W1[idx] = v;
}

// transposed bf16 hi/lo weight: Wt[n][k]: k<256:Wl, 256-511:Wr, +512: lo parts
__global__ void k_buildWt(const float* __restrict__ Wl, const float* __restrict__ Wr,
                          __nv_bfloat16* __restrict__ Wt, int ncols) {
    int idx = blockIdx.x * blockDim.x + threadIdx.x;
    if (idx >= ncols * 512) return;
    int n = idx / 512, k = idx - n * 512;
    float v = (k < 256) ? Wl[k * ncols + n] : Wr[(k - 256) * ncols + n];
    __nv_bfloat16 hi = __float2bfloat16(v);
    __nv_bfloat16 lo = __float2bfloat16(v - __bfloat162float(hi));
    Wt[n * 1024 + k] = hi;
    Wt[n * 1024 + 512 + k] = lo;
}

// ---------------- helpers ---------------------------------------------------
__device__ __forceinline__ void acc8(float* a, uint4 h, uint4 l) {
    const __nv_bfloat162* hp = (const __nv_bfloat162*)&h;
    const __nv_bfloat162* lp = (const __nv_bfloat162*)&l;
    #pragma unroll
    for (int p = 0; p < 4; p++) {
        float2 hf = __bfloat1622float2(hp[p]);
        float2 lf = __bfloat1622float2(lp[p]);
        a[2 * p]     += hf.x + lf.x;
        a[2 * p + 1] += hf.y + lf.y;
    }
}

// ---------------- layer-1 concat build --------------------------------------
__global__ void k_agg15(const float* __restrict__ x, float* __restrict__ xc) {
    int warp = (blockIdx.x * blockDim.x + threadIdx.x) >> 5;
    if (warp >= N_NODES) return;
    int lane = threadIdx.x & 31;
    int s = g_off[warp], e = g_off[warp + 1];
    float acc = 0.f;
    for (int i = s; i < e; i++) {
        int sn = g_ssrc[i];
        if (lane < D_IN) acc += x[sn * D_IN + lane];
    }
    float inv = 1.f / (float)max(e - s, 1);
    float* row = xc + warp * 32;
    if (lane < D_IN) {
        row[lane] = acc * inv;
        row[D_IN + lane] = x[warp * D_IN + lane];
    }
    if (lane == 15) { row[30] = 0.f; row[31] = 0.f; }
}

// ---------------- mean aggregation (layers 2-4 input) ------------------------
// gather neighbors' (x_hi, x_lo) slices from prev buffer, fp32 mean, hi/lo split
__global__ void k_aggmean(const __nv_bfloat16* __restrict__ Ap, __nv_bfloat16* __restrict__ Am) {
    int warp = (blockIdx.x * blockDim.x + threadIdx.x) >> 5;
    if (warp >= N_NODES) return;
    int lane = threadIdx.x & 31;
    int s = g_off[warp], e = g_off[warp + 1];
    float acc[8];
    #pragma unroll
    for (int j = 0; j < 8; j++) acc[j] = 0.f;
    int i = s;
    for (; i + 1 < e; i += 2) {
        int s0 = g_ssrc[i], s1 = g_ssrc[i + 1];
        uint4 h0 = *(const uint4*)(Ap + (size_t)s0 * 1024 + 256 + lane * 8);
        uint4 l0 = *(const uint4*)(Ap + (size_t)s0 * 1024 + 768 + lane * 8);
        uint4 h1 = *(const uint4*)(Ap + (size_t)s1 * 1024 + 256 + lane * 8);
        uint4 l1 = *(const uint4*)(Ap + (size_t)s1 * 1024 + 768 + lane * 8);
        acc8(acc, h0, l0);
        acc8(acc, h1, l1);
    }
    if (i < e) {
        int s0 = g_ssrc[i];
        uint4 h0 = *(const uint4*)(Ap + (size_t)s0 * 1024 + 256 + lane * 8);
        uint4 l0 = *(const uint4*)(Ap + (size_t)s0 * 1024 + 768 + lane * 8);
        acc8(acc, h0, l0);
    }
    float inv = 1.f / (float)max(e - s, 1);
    uint32_t hi[4], lo[4];
    #pragma unroll
    for (int p = 0; p < 4; p++) {
        float m0 = acc[2 * p] * inv, m1 = acc[2 * p + 1] * inv;
        __nv_bfloat162 h = __floats2bfloat162_rn(m0, m1);
        float r0 = m0 - __bfloat162float(__low2bfloat16(h));
        float r1 = m1 - __bfloat162float(__high2bfloat16(h));
        __nv_bfloat162 l = __floats2bfloat162_rn(r0, r1);
        hi[p] = *(uint32_t*)&h;
        lo[p] = *(uint32_t*)&l;
    }
    *(uint4*)(Am + (size_t)warp * 1024 + lane * 8)       = *(uint4*)hi;
    *(uint4*)(Am + (size_t)warp * 1024 + 512 + lane * 8) = *(uint4*)lo;
}

// ---------------- layer-1 fused SIMT GEMM + LN + GELU + split ----------------
// 512 threads; warp w owns rows row0+w*8..+7; lane covers cols {lane + 32j}
__global__ __launch_bounds__(512)
void k_gemm1f(const float* __restrict__ xc, const float* __restrict__ W1,
              const float* __restrict__ bias, const float* __restrict__ gam,
              const float* __restrict__ bet, __nv_bfloat16* __restrict__ Anext) {
    extern __shared__ float sm1[];
    float* As = sm1;               // [32][132]  (k, row) padded
    float* Ws = sm1 + 32 * 132;    // [32][256]
    int tid = threadIdx.x, lane = tid & 31, warp = tid >> 5;
    int row0 = blockIdx.x * 128;

    #pragma unroll
    for (int i = 0; i < 2; i++) {
        int t = tid + i * 512;
        int r = t >> 3, kq = (t & 7) * 4;
        float4 v = *(const float4*)&xc[(size_t)(row0 + r) * 32 + kq];
        As[(kq + 0) * 132 + r] = v.x; As[(kq + 1) * 132 + r] = v.y;
        As[(kq + 2) * 132 + r] = v.z; As[(kq + 3) * 132 + r] = v.w;
    }
    #pragma unroll
    for (int i = 0; i < 4; i++) {
        int t = tid + i * 512;
        int k = t >> 6, c4 = (t & 63) * 4;
        *(float4*)&Ws[k * 256 + c4] = *(const float4*)&W1[k * 256 + c4];
    }
    __syncthreads();

    float acc[8][8];
    #pragma unroll
    for (int r = 0; r < 8; r++)
        #pragma unroll
        for (int j = 0; j < 8; j++) acc[r][j] = 0.f;
    #pragma unroll 8
    for (int k = 0; k < 32; k++) {
        float a[8], b[8];
        #pragma unroll
        for (int r = 0; r < 8; r++) a[r] = As[k * 132 + warp * 8 + r];
        #pragma unroll
        for (int j = 0; j < 8; j++) b[j] = Ws[k * 256 + j * 32 + lane];
        #pragma unroll
        for (int r = 0; r < 8; r++)
            #pragma unroll
            for (int j = 0; j < 8; j++) acc[r][j] += a[r] * b[j];
    }
    // bias
    #pragma unroll
    for (int j = 0; j < 8; j++) {
        float bj = bias[j * 32 + lane];
        #pragma unroll
        for (int r = 0; r < 8; r++) acc[r][j] += bj;
    }
    // per-row LN + GELU + split (row fully inside warp)
    #pragma unroll
    for (int r = 0; r < 8; r++) {
        float s = 0.f, q = 0.f;
        #pragma unroll
        for (int j = 0; j < 8; j++) { s += acc[r][j]; q += acc[r][j] * acc[r][j]; }
        #pragma unroll
        for (int o = 16; o; o >>= 1) {
            s += __shfl_xor_sync(0xffffffffu, s, o);
            q += __shfl_xor_sync(0xffffffffu, q, o);
        }
        float mu = s * (1.f / 256.f);
        float var = fmaxf(q * (1.f / 256.f) - mu * mu, 0.f);
        float rs = rsqrtf(var + LN_EPS);
        size_t rowoff = (size_t)(row0 + warp * 8 + r) * 1024;
        #pragma unroll
        for (int j = 0; j < 8; j++) {
            int c = j * 32 + lane;
            float y = (acc[r][j] - mu) * rs * gam[c] + bet[c];
            float o = y * normcdff(y);
            __nv_bfloat16 h = __float2bfloat16(o);
            __nv_bfloat16 l = __float2bfloat16(o - __bfloat162float(h));
            Anext[rowoff + 256 + c] = h;
            Anext[rowoff + 768 + c] = l;
        }
    }
}

// ---------------- fused tensor-core GEMM + bias + LN + GELU ------------------
// BM=128, BN=NT (full layer width), 512 threads (16 warps 4m x 4n)
// MODE 0: write x_hi/x_lo into Anext.  MODE 1: pool atomics into out.
template<int NT, int MODE>
__global__ __launch_bounds__(512)
void k_gemm_f(const __nv_bfloat16* __restrict__ A, const __nv_bfloat16* __restrict__ Wt,
              const float* __restrict__ bias, const float* __restrict__ gam,
              const float* __restrict__ bet, __nv_bfloat16* __restrict__ Anext,
              float* __restrict__ out, const int* __restrict__ batch) {
    extern __shared__ char smem[];
    uint32_t sb = smem_to_u32(smem);
    constexpr int BBYTES = NT * 128;
    constexpr int STAGE = 16384 + BBYTES;
    constexpr int NB = NT / 32;      // per-warp 8-col blocks
    constexpr int NB4 = NT / 64;     // per-warp ldsm groups
    constexpr int BAND = NT / 4;     // per-warp col band
    float2* red = (float2*)(smem + 2 * STAGE);   // [4 warp_n][128 rows]

    int tid = threadIdx.x, lane = tid & 31, warp = tid >> 5;
    int warp_m = warp & 3, warp_n = warp >> 2;
    int row0 = blockIdx.x * 128;

    float acc[2][NB][4];
    #pragma unroll
    for (int mi = 0; mi < 2; mi++)
        #pragma unroll
        for (int nb = 0; nb < NB; nb++)
            #pragma unroll
            for (int r = 0; r < 4; r++) acc[mi][nb][r] = 0.f;

    auto issue = [&](int c, int s) {
        int kA = ((c < 16) ? c : c - 16) * 64;
        int kB = ((c < 8) ? c : c - 8) * 64;
        uint32_t dA = sb + s * STAGE;
        uint32_t dB = dA + 16384;
        const __nv_bfloat16* pa = A + (size_t)row0 * 1024 + kA;
        const __nv_bfloat16* pb = Wt + kB;
        #pragma unroll
        for (int i = 0; i < 2; i++) {
            int t = tid + i * 512;
            int r = t >> 3, seg = t & 7;
            CP16(dA + SWZ(r * 128 + seg * 16), pa + (size_t)r * 1024 + seg * 8);
        }
        #pragma unroll
        for (int i = 0; i < NB4; i++) {
            int t = tid + i * 512;
            int r = t >> 3, seg = t & 7;
            CP16(dB + SWZ(r * 128 + seg * 16), pb + (size_t)r * 1024 + seg * 8);
        }
        CP_COMMIT();
    };

    issue(0, 0);
    for (int c = 0; c < 24; c++) {
        int s = c & 1;
        if (c < 23) { issue(c + 1, s ^ 1); CP_WAIT(1); }
        else        { CP_WAIT(0); }
        __syncthreads();
        uint32_t sA = sb + s * STAGE, sB = sA + 16384;
        #pragma unroll
        for (int kk = 0; kk < 64; kk += 16) {
            uint32_t a[2][4], b[NB4][4];
            #pragma unroll
            for (int mi = 0; mi < 2; mi++) {
                int r = warp_m * 32 + mi * 16 + (lane & 15);
                int cb = (kk + (lane >> 4) * 8) * 2;
                LDSM_X4(a[mi][0], a[mi][1], a[mi][2], a[mi][3], sA + SWZ(r * 128 + cb));
            }
            #pragma unroll
            for (int nb4 = 0; nb4 < NB4; nb4++) {
                int g = lane >> 3;
                int n = warp_n * BAND + nb4 * 16 + (lane & 7) + (g >> 1) * 8;
                int kb = (kk + (g & 1) * 8) * 2;
                LDSM_X4(b[nb4][0], b[nb4][1], b[nb4][2], b[nb4][3], sB + SWZ(n * 128 + kb));
            }
            #pragma unroll
            for (int mi = 0; mi < 2; mi++)
                #pragma unroll
                for (int nb = 0; nb < NB; nb++) {
                    uint32_t b0 = b[nb >> 1][(nb & 1) * 2];
                    uint32_t b1 = b[nb >> 1][(nb & 1) * 2 + 1];
                    MMA_BF16(acc[mi][nb], a[mi], b0, b1);
                }
        }
        __syncthreads();
    }

    int tr = lane >> 2, tc = lane & 3;
    // add bias into acc
    #pragma unroll
    for (int nb = 0; nb < NB; nb++) {
        int cg = warp_n * BAND + nb * 8 + tc * 2;
        float bx = bias[cg], by = bias[cg + 1];
        #pragma unroll
        for (int mi = 0; mi < 2; mi++) {
            acc[mi][nb][0] += bx; acc[mi][nb][1] += by;
            acc[mi][nb][2] += bx; acc[mi][nb][3] += by;
        }
    }
    // LN stats: per (mi, h) row partials, quad reduce, cross-warp via smem
    float ss[2][2], qq[2][2];
    #pragma unroll
    for (int mi = 0; mi < 2; mi++)
        #pragma unroll
        for (int h = 0; h < 2; h++) {
            float s = 0.f, q = 0.f;
            #pragma unroll
            for (int nb = 0; nb < NB; nb++) {
                float v0 = acc[mi][nb][2 * h], v1 = acc[mi][nb][2 * h + 1];
                s += v0 + v1; q += v0 * v0 + v1 * v1;
            }
            s += __shfl_xor_sync(0xffffffffu, s, 1);
            q += __shfl_xor_sync(0xffffffffu, q, 1);
            s += __shfl_xor_sync(0xffffffffu, s, 2);
            q += __shfl_xor_sync(0xffffffffu, q, 2);
            ss[mi][h] = s; qq[mi][h] = q;
        }
    if (tc == 0) {
        #pragma unroll
        for (int mi = 0; mi < 2; mi++)
            #pragma unroll
            for (int h = 0; h < 2; h++)
                red[warp_n * 128 + warp_m * 32 + mi * 16 + h * 8 + tr] =
                    make_float2(ss[mi][h], qq[mi][h]);
    }
    __syncthreads();
    float mean[2][2], rstd[2][2];
    #pragma unroll
    for (int mi = 0; mi < 2; mi++)
        #pragma unroll
        for (int h = 0; h < 2; h++) {
            int rloc = warp_m * 32 + mi * 16 + h * 8 + tr;
            float S = 0.f, Q = 0.f;
            #pragma unroll
            for (int wn = 0; wn < 4; wn++) {
                float2 p = red[wn * 128 + rloc];
                S += p.x; Q += p.y;
            }
            float mu = S * (1.f / NT);
            float var = fmaxf(Q * (1.f / NT) - mu * mu, 0.f);
            mean[mi][h] = mu;
            rstd[mi][h] = rsqrtf(var + LN_EPS);
        }
    // GELU + output
    #pragma unroll
    for (int nb = 0; nb < NB; nb++) {
        int cg = warp_n * BAND + nb * 8 + tc * 2;
        float g0 = gam[cg], g1 = gam[cg + 1];
        float t0 = bet[cg], t1 = bet[cg + 1];
        #pragma unroll
        for (int mi = 0; mi < 2; mi++)
            #pragma unroll
            for (int h = 0; h < 2; h++) {
                int rg = row0 + warp_m * 32 + mi * 16 + h * 8 + tr;
                float mu = mean[mi][h], rs = rstd[mi][h];
                float y0 = (acc[mi][nb][2 * h]     - mu) * rs * g0 + t0;
                float y1 = (acc[mi][nb][2 * h + 1] - mu) * rs * g1 + t1;
                float o0 = y0 * normcdff(y0);
                float o1 = y1 * normcdff(y1);
                if (MODE == 0) {
                    __nv_bfloat162 hh = __floats2bfloat162_rn(o0, o1);
                    float r0 = o0 - __bfloat162float(__low2bfloat16(hh));
                    float r1 = o1 - __bfloat162float(__high2bfloat16(hh));
                    __nv_bfloat162 ll = __floats2bfloat162_rn(r0, r1);
                    *(__nv_bfloat162*)(Anext + (size_t)rg * 1024 + 256 + cg) = hh;
                    *(__nv_bfloat162*)(Anext + (size_t)rg * 1024 + 768 + cg) = ll;
                } else {
                    if (rg < N_NODES) {
                        int bidx = batch[rg];
                        atomicAdd(&out[bidx * D_OUT + cg],     o0);
                        atomicAdd(&out[bidx * D_OUT + cg + 1], o1);
                    }
                }
            }
    }
}

// ---------------- final division --------------------------------------------
__global__ void k_poolfin(float* __restrict__ out) {
    int i = blockIdx.x * blockDim.x + threadIdx.x;
    if (i < N_BATCH * D_OUT) {
        int c = g_bcnt[i / D_OUT];
        out[i] /= (float)max(c, 1);
    }
}

// ---------------- launch -----------------------------------------------------
extern "C" void kernel_launch(void* const* d_in, const int* in_sizes, int n_in,
                              void* d_out, int out_size) {
    const float* x     = (const float*)d_in[0];
    const int*   ei    = (const int*)d_in[1];
    const int*   src   = ei;
    const int*   dst   = ei + N_EDGES;
    const int*   batch = (const int*)d_in[2];
    const float* Wl1 = (const float*)d_in[3],  *Wr1 = (const float*)d_in[4];
    const float* b1  = (const float*)d_in[5],  *g1  = (const float*)d_in[6],  *bt1 = (const float*)d_in[7];
    const float* Wl2 = (const float*)d_in[8],  *Wr2 = (const float*)d_in[9];
    const float* b2  = (const float*)d_in[10], *g2  = (const float*)d_in[11], *bt2 = (const float*)d_in[12];
    const float* Wl3 = (const float*)d_in[13], *Wr3 = (const float*)d_in[14];
    const float* b3  = (const float*)d_in[15], *g3  = (const float*)d_in[16], *bt3 = (const float*)d_in[17];
    const float* Wl4 = (const float*)d_in[18], *Wr4 = (const float*)d_in[19];
    const float* b4  = (const float*)d_in[20], *g4  = (const float*)d_in[21], *bt4 = (const float*)d_in[22];
    float* out = (float*)d_out;

    float *xc1, *W1;
    __nv_bfloat16 *AbfA, *AbfB, *WtAll;
    cudaGetSymbolAddress((void**)&xc1,   g_xc1);
    cudaGetSymbolAddress((void**)&W1,    g_W1);
    cudaGetSymbolAddress((void**)&AbfA,  g_AbfA);
    cudaGetSymbolAddress((void**)&AbfB,  g_AbfB);
    cudaGetSymbolAddress((void**)&WtAll, g_WtAll);
    __nv_bfloat16* Wt2 = WtAll;
    __nv_bfloat16* Wt3 = WtAll + (size_t)256 * 1024;
    __nv_bfloat16* Wt4 = WtAll + (size_t)512 * 1024;

    const int TB = 256;
    int gridE = (N_EDGES + TB - 1) / TB;
    int gridN = (N_NODES + TB - 1) / TB;
    int gridWarpN = (N_NODES * 32 + TB - 1) / TB;
    int gridTiles = N_PAD / 128;   // 391

    const int SM1   = (32 * 132 + 32 * 256) * 4;           // 49664
    const int SM256 = 2 * (16384 + 256 * 128) + 4096;      // 102400
    const int SM128 = 2 * (16384 + 128 * 128) + 4096;      // 69632
    cudaFuncSetAttribute(k_gemm1f, cudaFuncAttributeMaxDynamicSharedMemorySize, SM1);
    cudaFuncSetAttribute(k_gemm_f<256, 0>, cudaFuncAttributeMaxDynamicSharedMemorySize, SM256);
    cudaFuncSetAttribute(k_gemm_f<128, 1>, cudaFuncAttributeMaxDynamicSharedMemorySize, SM128);

    // ---- setup ----
    k_zero<<<gridN, TB>>>(out);
    k_hist_deg<<<gridE, TB>>>(dst);
    k_hist_batch<<<gridN, TB>>>(batch);
    k_scanA<<<NB_SCAN, 1024>>>();
    k_scanB<<<1, 64>>>();
    k_scanC<<<NB_SCAN, 1024>>>();
    k_scatter<<<gridE, TB>>>(src, dst);
    k_buildW1<<<(32 * D_HID + TB - 1) / TB, TB>>>(Wl1, Wr1);
    k_buildWt<<<(D_HID * 512 + TB - 1) / TB, TB>>>(Wl2, Wr2, Wt2, D_HID);
    k_buildWt<<<(D_HID * 512 + TB - 1) / TB, TB>>>(Wl3, Wr3, Wt3, D_HID);
    k_buildWt<<<(D_OUT * 512 + TB - 1) / TB, TB>>>(Wl4, Wr4, Wt4, D_OUT);

    // ---- layer 1: SIMT K=32 fused (writes x-part of AbfA) ----
    k_agg15<<<gridWarpN, TB>>>(x, xc1);
    k_gemm1f<<<gridTiles, 512, SM1>>>(xc1, W1, b1, g1, bt1, AbfA);

    // ---- layer 2 ----
    k_aggmean<<<gridWarpN, TB>>>(AbfA, AbfA);
    k_gemm_f<256, 0><<<gridTiles, 512, SM256>>>(AbfA, Wt2, b2, g2, bt2, AbfB, nullptr, nullptr);

    // ---- layer 3 ----
    k_aggmean<<<gridWarpN, TB>>>(AbfB, AbfB);
    k_gemm_f<256, 0><<<gridTiles, 512, SM256>>>(AbfB, Wt3, b3, g3, bt3, AbfA, nullptr, nullptr);

    // ---- layer 4: fused pool ----
    k_aggmean<<<gridWarpN, TB>>>(AbfA, AbfA);
    k_gemm_f<128, 1><<<gridTiles, 512, SM128>>>(AbfA, Wt4, b4, g4, bt4, nullptr, out, batch);

    k_poolfin<<<(N_BATCH * D_OUT + TB - 1) / TB, TB>>>(out);
}

// round 6
// speedup vs baseline: 1.0646x; 1.0646x over previous
#include <cuda_runtime.h>
#include <cuda_bf16.h>
#include <cuda_fp16.h>
#include <math.h>
#include <stdint.h>

#define N_NODES 50000
#define N_PAD   50048            // 391 * 128
#define N_EDGES 800000
#define N_BATCH 128
#define D_IN    15
#define D_HID   256
#define D_OUT   128
#define LN_EPS  1e-5f
#define NB_SCAN 49               // ceil(50000/1024)

// ---------------- device scratch -------------------------------------------
// Activation buffers: row = 1024 bf16 = [mean_hi(0:256) | x_hi(256:512) | mean_lo(512:768) | x_lo(768:1024)]
__device__ __nv_bfloat16 g_AbfA[(size_t)N_PAD * 1024];  // 102 MB
__device__ __nv_bfloat16 g_AbfB[(size_t)N_PAD * 1024];  // 102 MB
__device__ __half        g_h16[(size_t)N_PAD * 256];    // 25.6 MB compact gather copy
__device__ __nv_bfloat16 g_WtAll[(256 + 256 + 128) * 1024]; // W^T bf16 hi/lo, layers 2,3,4
__device__ float g_xc1[N_PAD * 32];                   // layer-1 concat (K=32)
__device__ float g_W1[32 * D_HID];                    // layer-1 fp32 combined W
__device__ int   g_ssrc[N_EDGES];
__device__ int   g_off [N_NODES + 1];
__device__ int   g_cur [N_NODES];
__device__ int   g_deg [N_NODES];
__device__ int   g_bsum[64];
__device__ int   g_bcnt[N_BATCH];

// ---------------- PTX helpers ----------------------------------------------
__device__ __forceinline__ uint32_t smem_to_u32(const void* p) {
    uint32_t a;
    asm("{ .reg .u64 t; cvta.to.shared.u64 t, %1; cvt.u32.u64 %0, t; }" : "=r"(a) : "l"(p));
    return a;
}
#define CP16(dst, src) \
    asm volatile("cp.async.cg.shared.global [%0], [%1], 16;" :: "r"((uint32_t)(dst)), "l"(src) : "memory")
#define CP_COMMIT() asm volatile("cp.async.commit_group;" ::: "memory")
#define CP_WAIT(n)  asm volatile("cp.async.wait_group %0;" :: "n"(n) : "memory")
#define SWZ(b) ((b) ^ (((b) >> 3) & 0x70))
#define LDSM_X4(r0, r1, r2, r3, addr) \
    asm volatile("ldmatrix.sync.aligned.m8n8.x4.shared.b16 {%0,%1,%2,%3}, [%4];" \
                 : "=r"(r0), "=r"(r1), "=r"(r2), "=r"(r3) : "r"(addr))
#define MMA_BF16(d, a, b0, b1) \
    asm volatile("mma.sync.aligned.m16n8k16.row.col.f32.bf16.bf16.f32 " \
                 "{%0,%1,%2,%3}, {%4,%5,%6,%7}, {%8,%9}, {%0,%1,%2,%3};" \
                 : "+f"((d)[0]), "+f"((d)[1]), "+f"((d)[2]), "+f"((d)[3]) \
                 : "r"((a)[0]), "r"((a)[1]), "r"((a)[2]), "r"((a)[3]), \
                   "r"(b0), "r"(b1))

// ---------------- setup kernels --------------------------------------------
__global__ void k_zero(float* out) {
    int i = blockIdx.x * blockDim.x + threadIdx.x;
    if (i < N_NODES) g_deg[i] = 0;
    if (i < N_BATCH) g_bcnt[i] = 0;
    if (i < N_BATCH * D_OUT) out[i] = 0.f;
}
__global__ void k_hist_deg(const int* __restrict__ dst) {
    int e = blockIdx.x * blockDim.x + threadIdx.x;
    if (e < N_EDGES) atomicAdd(&g_deg[dst[e]], 1);
}
__global__ void k_hist_batch(const int* __restrict__ batch) {
    int n = blockIdx.x * blockDim.x + threadIdx.x;
    if (n < N_NODES) atomicAdd(&g_bcnt[batch[n]], 1);
}
__global__ void k_scanA() {
    __shared__ int ws[32];
    int tid = threadIdx.x, lane = tid & 31, wid = tid >> 5;
    int i = blockIdx.x * 1024 + tid;
    int v = (i < N_NODES) ? g_deg[i] : 0;
    int x = v;
    #pragma unroll
    for (int o = 1; o < 32; o <<= 1) {
        int t = __shfl_up_sync(0xffffffffu, x, o);
        if (lane >= o) x += t;
    }
    if (lane == 31) ws[wid] = x;
    __syncthreads();
    if (wid == 0) {
        int y = ws[lane];
        #pragma unroll
        for (int o = 1; o < 32; o <<= 1) {
            int t = __shfl_up_sync(0xffffffffu, y, o);
            if (lane >= o) y += t;
        }
        ws[lane] = y;
    }
    __syncthreads();
    int incl = x + (wid ? ws[wid - 1] : 0);
    if (i < N_NODES) g_off[i] = incl - v;
    if (tid == 1023) g_bsum[blockIdx.x] = incl;
}
__global__ void k_scanB() {
    __shared__ int s[64];
    int tid = threadIdx.x;
    s[tid] = (tid < NB_SCAN) ? g_bsum[tid] : 0;
    __syncthreads();
    if (tid == 0) {
        int acc = 0;
        for (int i = 0; i < NB_SCAN; i++) { int t = s[i]; s[i] = acc; acc += t; }
        g_off[N_NODES] = acc;
    }
    __syncthreads();
    if (tid < NB_SCAN) g_bsum[tid] = s[tid];
}
__global__ void k_scanC() {
    int i = blockIdx.x * 1024 + threadIdx.x;
    if (i < N_NODES) {
        int o = g_off[i] + g_bsum[blockIdx.x];
        g_off[i] = o;
        g_cur[i] = o;
    }
}
__global__ void k_scatter(const int* __restrict__ src, const int* __restrict__ dst) {
    int e = blockIdx.x * blockDim.x + threadIdx.x;
    if (e < N_EDGES) {
        int p = atomicAdd(&g_cur[dst[e]], 1);
        g_ssrc[p] = src[e];
    }
}

// layer-1 combined weight (fp32): rows [0,15)=Wl1, [15,30)=Wr1, [30,32)=0
__global__ void k_buildW1(const float* __restrict__ Wl, const float* __restrict__ Wr) {
    int idx = blockIdx.x * blockDim.x + threadIdx.x;
    if (idx >= 32 * D_HID) return;
    int k = idx / D_HID, n = idx - k * D_HID;
    float v = 0.f;
    if (k < D_IN)          v = Wl[k * D_HID + n];
    else if (k < 2 * D_IN) v = Wr[(k - D_IN) * D_HID + n];
    g_W1[idx] = v;
}

// transposed bf16 hi/lo weight: Wt[n][k]: k<256:Wl, 256-511:Wr, +512: lo parts
__global__ void k_buildWt(const float* __restrict__ Wl, const float* __restrict__ Wr,
                          __nv_bfloat16* __restrict__ Wt, int ncols) {
    int idx = blockIdx.x * blockDim.x + threadIdx.x;
    if (idx >= ncols * 512) return;
    int n = idx / 512, k = idx - n * 512;
    float v = (k < 256) ? Wl[k * ncols + n] : Wr[(k - 256) * ncols + n];
    __nv_bfloat16 hi = __float2bfloat16(v);
    __nv_bfloat16 lo = __float2bfloat16(v - __bfloat162float(hi));
    Wt[n * 1024 + k] = hi;
    Wt[n * 1024 + 512 + k] = lo;
}

// ---------------- layer-1 concat build --------------------------------------
__global__ void k_agg15(const float* __restrict__ x, float* __restrict__ xc) {
    int warp = (blockIdx.x * blockDim.x + threadIdx.x) >> 5;
    if (warp >= N_NODES) return;
    int lane = threadIdx.x & 31;
    int s = g_off[warp], e = g_off[warp + 1];
    float acc = 0.f;
    for (int i = s; i < e; i++) {
        int sn = g_ssrc[i];
        if (lane < D_IN) acc += x[sn * D_IN + lane];
    }
    float inv = 1.f / (float)max(e - s, 1);
    float* row = xc + warp * 32;
    if (lane < D_IN) {
        row[lane] = acc * inv;
        row[D_IN + lane] = x[warp * D_IN + lane];
    }
    if (lane == 15) { row[30] = 0.f; row[31] = 0.f; }
}

// ---------------- mean aggregation (layers 2-4 input) ------------------------
// gather neighbors' fp16 compact rows, fp32 mean, hi/lo split into mean slots
__device__ __forceinline__ void acch(float* a, uint4 h) {
    const __half2* hp = (const __half2*)&h;
    #pragma unroll
    for (int p = 0; p < 4; p++) {
        float2 f = __half22float2(hp[p]);
        a[2 * p]     += f.x;
        a[2 * p + 1] += f.y;
    }
}
__global__ void k_aggmean(const __half* __restrict__ h16, __nv_bfloat16* __restrict__ Am) {
    int warp = (blockIdx.x * blockDim.x + threadIdx.x) >> 5;
    if (warp >= N_NODES) return;
    int lane = threadIdx.x & 31;
    int s = g_off[warp], e = g_off[warp + 1];
    float acc[8];
    #pragma unroll
    for (int j = 0; j < 8; j++) acc[j] = 0.f;
    int i = s;
    for (; i + 3 < e; i += 4) {
        int s0 = g_ssrc[i], s1 = g_ssrc[i + 1], s2 = g_ssrc[i + 2], s3 = g_ssrc[i + 3];
        uint4 v0 = *(const uint4*)(h16 + (size_t)s0 * 256 + lane * 8);
        uint4 v1 = *(const uint4*)(h16 + (size_t)s1 * 256 + lane * 8);
        uint4 v2 = *(const uint4*)(h16 + (size_t)s2 * 256 + lane * 8);
        uint4 v3 = *(const uint4*)(h16 + (size_t)s3 * 256 + lane * 8);
        acch(acc, v0); acch(acc, v1); acch(acc, v2); acch(acc, v3);
    }
    for (; i < e; i++) {
        int s0 = g_ssrc[i];
        uint4 v0 = *(const uint4*)(h16 + (size_t)s0 * 256 + lane * 8);
        acch(acc, v0);
    }
    float inv = 1.f / (float)max(e - s, 1);
    uint32_t hi[4], lo[4];
    #pragma unroll
    for (int p = 0; p < 4; p++) {
        float m0 = acc[2 * p] * inv, m1 = acc[2 * p + 1] * inv;
        __nv_bfloat162 h = __floats2bfloat162_rn(m0, m1);
        float r0 = m0 - __bfloat162float(__low2bfloat16(h));
        float r1 = m1 - __bfloat162float(__high2bfloat16(h));
        __nv_bfloat162 l = __floats2bfloat162_rn(r0, r1);
        hi[p] = *(uint32_t*)&h;
        lo[p] = *(uint32_t*)&l;
    }
    *(uint4*)(Am + (size_t)warp * 1024 + lane * 8)       = *(uint4*)hi;
    *(uint4*)(Am + (size_t)warp * 1024 + 512 + lane * 8) = *(uint4*)lo;
}

// ---------------- layer-1 fused SIMT GEMM + LN + GELU + split ----------------
__global__ __launch_bounds__(512)
void k_gemm1f(const float* __restrict__ xc, const float* __restrict__ W1,
              const float* __restrict__ bias, const float* __restrict__ gam,
              const float* __restrict__ bet, __nv_bfloat16* __restrict__ Anext,
              __half* __restrict__ h16out) {
    extern __shared__ float sm1[];
    float* As = sm1;               // [32][132]  (k, row) padded
    float* Ws = sm1 + 32 * 132;    // [32][256]
    int tid = threadIdx.x, lane = tid & 31, warp = tid >> 5;
    int row0 = blockIdx.x * 128;

    #pragma unroll
    for (int i = 0; i < 2; i++) {
        int t = tid + i * 512;
        int r = t >> 3, kq = (t & 7) * 4;
        float4 v = *(const float4*)&xc[(size_t)(row0 + r) * 32 + kq];
        As[(kq + 0) * 132 + r] = v.x; As[(kq + 1) * 132 + r] = v.y;
        As[(kq + 2) * 132 + r] = v.z; As[(kq + 3) * 132 + r] = v.w;
    }
    #pragma unroll
    for (int i = 0; i < 4; i++) {
        int t = tid + i * 512;
        int k = t >> 6, c4 = (t & 63) * 4;
        *(float4*)&Ws[k * 256 + c4] = *(const float4*)&W1[k * 256 + c4];
    }
    __syncthreads();

    float acc[8][8];
    #pragma unroll
    for (int r = 0; r < 8; r++)
        #pragma unroll
        for (int j = 0; j < 8; j++) acc[r][j] = 0.f;
    #pragma unroll 8
    for (int k = 0; k < 32; k++) {
        float a[8], b[8];
        #pragma unroll
        for (int r = 0; r < 8; r++) a[r] = As[k * 132 + warp * 8 + r];
        #pragma unroll
        for (int j = 0; j < 8; j++) b[j] = Ws[k * 256 + j * 32 + lane];
        #pragma unroll
        for (int r = 0; r < 8; r++)
            #pragma unroll
            for (int j = 0; j < 8; j++) acc[r][j] += a[r] * b[j];
    }
    #pragma unroll
    for (int j = 0; j < 8; j++) {
        float bj = bias[j * 32 + lane];
        #pragma unroll
        for (int r = 0; r < 8; r++) acc[r][j] += bj;
    }
    #pragma unroll
    for (int r = 0; r < 8; r++) {
        float s = 0.f, q = 0.f;
        #pragma unroll
        for (int j = 0; j < 8; j++) { s += acc[r][j]; q += acc[r][j] * acc[r][j]; }
        #pragma unroll
        for (int o = 16; o; o >>= 1) {
            s += __shfl_xor_sync(0xffffffffu, s, o);
            q += __shfl_xor_sync(0xffffffffu, q, o);
        }
        float mu = s * (1.f / 256.f);
        float var = fmaxf(q * (1.f / 256.f) - mu * mu, 0.f);
        float rs = rsqrtf(var + LN_EPS);
        int rg = row0 + warp * 8 + r;
        size_t rowoff = (size_t)rg * 1024;
        #pragma unroll
        for (int j = 0; j < 8; j++) {
            int c = j * 32 + lane;
            float y = (acc[r][j] - mu) * rs * gam[c] + bet[c];
            float o = y * normcdff(y);
            __nv_bfloat16 h = __float2bfloat16(o);
            __nv_bfloat16 l = __float2bfloat16(o - __bfloat162float(h));
            Anext[rowoff + 256 + c] = h;
            Anext[rowoff + 768 + c] = l;
            h16out[(size_t)rg * 256 + c] = __float2half(o);
        }
    }
}

// ---------------- fused tensor-core GEMM + bias + LN + GELU ------------------
// BM=128, BN=NT (full layer width), 512 threads (16 warps 4m x 4n)
// MODE 0: write x_hi/x_lo + fp16 copy.  MODE 1: pool atomics into out.
template<int NT, int MODE>
__global__ __launch_bounds__(512)
void k_gemm_f(const __nv_bfloat16* __restrict__ A, const __nv_bfloat16* __restrict__ Wt,
              const float* __restrict__ bias, const float* __restrict__ gam,
              const float* __restrict__ bet, __nv_bfloat16* __restrict__ Anext,
              __half* __restrict__ h16out,
              float* __restrict__ out, const int* __restrict__ batch) {
    extern __shared__ char smem[];
    uint32_t sb = smem_to_u32(smem);
    constexpr int BBYTES = NT * 128;
    constexpr int STAGE = 16384 + BBYTES;
    constexpr int NB = NT / 32;
    constexpr int NB4 = NT / 64;
    constexpr int BAND = NT / 4;
    float2* red = (float2*)(smem + 2 * STAGE);   // [4 warp_n][128 rows]

    int tid = threadIdx.x, lane = tid & 31, warp = tid >> 5;
    int warp_m = warp & 3, warp_n = warp >> 2;
    int row0 = blockIdx.x * 128;

    float acc[2][NB][4];
    #pragma unroll
    for (int mi = 0; mi < 2; mi++)
        #pragma unroll
        for (int nb = 0; nb < NB; nb++)
            #pragma unroll
            for (int r = 0; r < 4; r++) acc[mi][nb][r] = 0.f;

    auto issue = [&](int c, int s) {
        int kA = ((c < 16) ? c : c - 16) * 64;
        int kB = ((c < 8) ? c : c - 8) * 64;
        uint32_t dA = sb + s * STAGE;
        uint32_t dB = dA + 16384;
        const __nv_bfloat16* pa = A + (size_t)row0 * 1024 + kA;
        const __nv_bfloat16* pb = Wt + kB;
        #pragma unroll
        for (int i = 0; i < 2; i++) {
            int t = tid + i * 512;
            int r = t >> 3, seg = t & 7;
            CP16(dA + SWZ(r * 128 + seg * 16), pa + (size_t)r * 1024 + seg * 8);
        }
        #pragma unroll
        for (int i = 0; i < NB4; i++) {
            int t = tid + i * 512;
            int r = t >> 3, seg = t & 7;
            CP16(dB + SWZ(r * 128 + seg * 16), pb + (size_t)r * 1024 + seg * 8);
        }
        CP_COMMIT();
    };

    issue(0, 0);
    for (int c = 0; c < 24; c++) {
        int s = c & 1;
        if (c < 23) { issue(c + 1, s ^ 1); CP_WAIT(1); }
        else        { CP_WAIT(0); }
        __syncthreads();
        uint32_t sA = sb + s * STAGE, sB = sA + 16384;
        #pragma unroll
        for (int kk = 0; kk < 64; kk += 16) {
            uint32_t a[2][4], b[NB4][4];
            #pragma unroll
            for (int mi = 0; mi < 2; mi++) {
                int r = warp_m * 32 + mi * 16 + (lane & 15);
                int cb = (kk + (lane >> 4) * 8) * 2;
                LDSM_X4(a[mi][0], a[mi][1], a[mi][2], a[mi][3], sA + SWZ(r * 128 + cb));
            }
            #pragma unroll
            for (int nb4 = 0; nb4 < NB4; nb4++) {
                int g = lane >> 3;
                int n = warp_n * BAND + nb4 * 16 + (lane & 7) + (g >> 1) * 8;
                int kb = (kk + (g & 1) * 8) * 2;
                LDSM_X4(b[nb4][0], b[nb4][1], b[nb4][2], b[nb4][3], sB + SWZ(n * 128 + kb));
            }
            #pragma unroll
            for (int mi = 0; mi < 2; mi++)
                #pragma unroll
                for (int nb = 0; nb < NB; nb++) {
                    uint32_t b0 = b[nb >> 1][(nb & 1) * 2];
                    uint32_t b1 = b[nb >> 1][(nb & 1) * 2 + 1];
                    MMA_BF16(acc[mi][nb], a[mi], b0, b1);
                }
        }
        __syncthreads();
    }

    int tr = lane >> 2, tc = lane & 3;
    #pragma unroll
    for (int nb = 0; nb < NB; nb++) {
        int cg = warp_n * BAND + nb * 8 + tc * 2;
        float bx = bias[cg], by = bias[cg + 1];
        #pragma unroll
        for (int mi = 0; mi < 2; mi++) {
            acc[mi][nb][0] += bx; acc[mi][nb][1] += by;
            acc[mi][nb][2] += bx; acc[mi][nb][3] += by;
        }
    }
    float ss[2][2], qq[2][2];
    #pragma unroll
    for (int mi = 0; mi < 2; mi++)
        #pragma unroll
        for (int h = 0; h < 2; h++) {
            float s = 0.f, q = 0.f;
            #pragma unroll
            for (int nb = 0; nb < NB; nb++) {
                float v0 = acc[mi][nb][2 * h], v1 = acc[mi][nb][2 * h + 1];
                s += v0 + v1; q += v0 * v0 + v1 * v1;
            }
            s += __shfl_xor_sync(0xffffffffu, s, 1);
            q += __shfl_xor_sync(0xffffffffu, q, 1);
            s += __shfl_xor_sync(0xffffffffu, s, 2);
            q += __shfl_xor_sync(0xffffffffu, q, 2);
            ss[mi][h] = s; qq[mi][h] = q;
        }
    if (tc == 0) {
        #pragma unroll
        for (int mi = 0; mi < 2; mi++)
            #pragma unroll
            for (int h = 0; h < 2; h++)
                red[warp_n * 128 + warp_m * 32 + mi * 16 + h * 8 + tr] =
                    make_float2(ss[mi][h], qq[mi][h]);
    }
    __syncthreads();
    float mean[2][2], rstd[2][2];
    #pragma unroll
    for (int mi = 0; mi < 2; mi++)
        #pragma unroll
        for (int h = 0; h < 2; h++) {
            int rloc = warp_m * 32 + mi * 16 + h * 8 + tr;
            float S = 0.f, Q = 0.f;
            #pragma unroll
            for (int wn = 0; wn < 4; wn++) {
                float2 p = red[wn * 128 + rloc];
                S += p.x; Q += p.y;
            }
            float mu = S * (1.f / NT);
            float var = fmaxf(Q * (1.f / NT) - mu * mu, 0.f);
            mean[mi][h] = mu;
            rstd[mi][h] = rsqrtf(var + LN_EPS);
        }
    #pragma unroll
    for (int nb = 0; nb < NB; nb++) {
        int cg = warp_n * BAND + nb * 8 + tc * 2;
        float g0 = gam[cg], g1 = gam[cg + 1];
        float t0 = bet[cg], t1 = bet[cg + 1];
        #pragma unroll
        for (int mi = 0; mi < 2; mi++)
            #pragma unroll
            for (int h = 0; h < 2; h++) {
                int rg = row0 + warp_m * 32 + mi * 16 + h * 8 + tr;
                float mu = mean[mi][h], rs = rstd[mi][h];
                float y0 = (acc[mi][nb][2 * h]     - mu) * rs * g0 + t0;
                float y1 = (acc[mi][nb][2 * h + 1] - mu) * rs * g1 + t1;
                float o0 = y0 * normcdff(y0);
                float o1 = y1 * normcdff(y1);
                if (MODE == 0) {
                    __nv_bfloat162 hh = __floats2bfloat162_rn(o0, o1);
                    float r0 = o0 - __bfloat162float(__low2bfloat16(hh));
                    float r1 = o1 - __bfloat162float(__high2bfloat16(hh));
                    __nv_bfloat162 ll = __floats2bfloat162_rn(r0, r1);
                    *(__nv_bfloat162*)(Anext + (size_t)rg * 1024 + 256 + cg) = hh;
                    *(__nv_bfloat162*)(Anext + (size_t)rg * 1024 + 768 + cg) = ll;
                    *(__half2*)(h16out + (size_t)rg * 256 + cg) = __floats2half2_rn(o0, o1);
                } else {
                    if (rg < N_NODES) {
                        int bidx = batch[rg];
                        atomicAdd(&out[bidx * D_OUT + cg],     o0);
                        atomicAdd(&out[bidx * D_OUT + cg + 1], o1);
                    }
                }
            }
    }
}

// ---------------- final division --------------------------------------------
__global__ void k_poolfin(float* __restrict__ out) {
    int i = blockIdx.x * blockDim.x + threadIdx.x;
    if (i < N_BATCH * D_OUT) {
        int c = g_bcnt[i / D_OUT];
        out[i] /= (float)max(c, 1);
    }
}

// ---------------- launch -----------------------------------------------------
extern "C" void kernel_launch(void* const* d_in, const int* in_sizes, int n_in,
                              void* d_out, int out_size) {
    const float* x     = (const float*)d_in[0];
    const int*   ei    = (const int*)d_in[1];
    const int*   src   = ei;
    const int*   dst   = ei + N_EDGES;
    const int*   batch = (const int*)d_in[2];
    const float* Wl1 = (const float*)d_in[3],  *Wr1 = (const float*)d_in[4];
    const float* b1  = (const float*)d_in[5],  *g1  = (const float*)d_in[6],  *bt1 = (const float*)d_in[7];
    const float* Wl2 = (const float*)d_in[8],  *Wr2 = (const float*)d_in[9];
    const float* b2  = (const float*)d_in[10], *g2  = (const float*)d_in[11], *bt2 = (const float*)d_in[12];
    const float* Wl3 = (const float*)d_in[13], *Wr3 = (const float*)d_in[14];
    const float* b3  = (const float*)d_in[15], *g3  = (const float*)d_in[16], *bt3 = (const float*)d_in[17];
    const float* Wl4 = (const float*)d_in[18], *Wr4 = (const float*)d_in[19];
    const float* b4  = (const float*)d_in[20], *g4  = (const float*)d_in[21], *bt4 = (const float*)d_in[22];
    float* out = (float*)d_out;

    float *xc1, *W1;
    __nv_bfloat16 *AbfA, *AbfB, *WtAll;
    __half *h16;
    cudaGetSymbolAddress((void**)&xc1,   g_xc1);
    cudaGetSymbolAddress((void**)&W1,    g_W1);
    cudaGetSymbolAddress((void**)&AbfA,  g_AbfA);
    cudaGetSymbolAddress((void**)&AbfB,  g_AbfB);
    cudaGetSymbolAddress((void**)&h16,   g_h16);
    cudaGetSymbolAddress((void**)&WtAll, g_WtAll);
    __nv_bfloat16* Wt2 = WtAll;
    __nv_bfloat16* Wt3 = WtAll + (size_t)256 * 1024;
    __nv_bfloat16* Wt4 = WtAll + (size_t)512 * 1024;

    const int TB = 256;
    int gridE = (N_EDGES + TB - 1) / TB;
    int gridN = (N_NODES + TB - 1) / TB;
    int gridWarpN = (N_NODES * 32 + TB - 1) / TB;
    int gridTiles = N_PAD / 128;   // 391

    const int SM1   = (32 * 132 + 32 * 256) * 4;           // 49664
    const int SM256 = 2 * (16384 + 256 * 128) + 4096;      // 102400
    const int SM128 = 2 * (16384 + 128 * 128) + 4096;      // 69632
    cudaFuncSetAttribute(k_gemm1f, cudaFuncAttributeMaxDynamicSharedMemorySize, SM1);
    cudaFuncSetAttribute(k_gemm_f<256, 0>, cudaFuncAttributeMaxDynamicSharedMemorySize, SM256);
    cudaFuncSetAttribute(k_gemm_f<128, 1>, cudaFuncAttributeMaxDynamicSharedMemorySize, SM128);

    // ---- setup ----
    k_zero<<<gridN, TB>>>(out);
    k_hist_deg<<<gridE, TB>>>(dst);
    k_hist_batch<<<gridN, TB>>>(batch);
    k_scanA<<<NB_SCAN, 1024>>>();
    k_scanB<<<1, 64>>>();
    k_scanC<<<NB_SCAN, 1024>>>();
    k_scatter<<<gridE, TB>>>(src, dst);
    k_buildW1<<<(32 * D_HID + TB - 1) / TB, TB>>>(Wl1, Wr1);
    k_buildWt<<<(D_HID * 512 + TB - 1) / TB, TB>>>(Wl2, Wr2, Wt2, D_HID);
    k_buildWt<<<(D_HID * 512 + TB - 1) / TB, TB>>>(Wl3, Wr3, Wt3, D_HID);
    k_buildWt<<<(D_OUT * 512 + TB - 1) / TB, TB>>>(Wl4, Wr4, Wt4, D_OUT);

    // ---- layer 1: SIMT K=32 fused (writes x-part of AbfA + fp16 copy) ----
    k_agg15<<<gridWarpN, TB>>>(x, xc1);
    k_gemm1f<<<gridTiles, 512, SM1>>>(xc1, W1, b1, g1, bt1, AbfA, h16);

    // ---- layer 2 ----
    k_aggmean<<<gridWarpN, TB>>>(h16, AbfA);
    k_gemm_f<256, 0><<<gridTiles, 512, SM256>>>(AbfA, Wt2, b2, g2, bt2, AbfB, h16, nullptr, nullptr);

    // ---- layer 3 ----
    k_aggmean<<<gridWarpN, TB>>>(h16, AbfB);
    k_gemm_f<256, 0><<<gridTiles, 512, SM256>>>(AbfB, Wt3, b3, g3, bt3, AbfA, h16, nullptr, nullptr);

    // ---- layer 4: fused pool ----
    k_aggmean<<<gridWarpN, TB>>>(h16, AbfA);
    k_gemm_f<128, 1><<<gridTiles, 512, SM128>>>(AbfA, Wt4, b4, g4, bt4, nullptr, nullptr, out, batch);

    k_poolfin<<<(N_BATCH * D_OUT + TB - 1) / TB, TB>>>(out);
}

// round 7
// speedup vs baseline: 1.6621x; 1.5612x over previous
#include <cuda_runtime.h>
#include <cuda_bf16.h>
#include <cuda_fp16.h>
#include <math.h>
#include <stdint.h>

#define N_NODES 50000
#define N_PAD   50048            // 391 * 128
#define N_EDGES 800000
#define N_BATCH 128
#define D_IN    15
#define D_HID   256
#define D_OUT   128
#define LN_EPS  1e-5f
#define NB_SCAN 49               // ceil(50000/1024)

// ---------------- device scratch -------------------------------------------
// Activation rows: 512 fp16 = [mean(0:256) | x(256:512)]
__device__ __half g_AA[(size_t)N_PAD * 512];          // 51 MB
__device__ __half g_AB[(size_t)N_PAD * 512];          // 51 MB
__device__ __half g_WtAll[(256 + 256 + 128) * 512];   // W^T fp16, layers 2,3,4
__device__ float g_xc1[N_PAD * 32];                   // layer-1 concat (K=32)
__device__ float g_W1[32 * D_HID];                    // layer-1 fp32 combined W
__device__ int   g_ssrc[N_EDGES];
__device__ int   g_off [N_NODES + 1];
__device__ int   g_cur [N_NODES];
__device__ int   g_deg [N_NODES];
__device__ int   g_bsum[64];
__device__ int   g_bcnt[N_BATCH];

// ---------------- PTX helpers ----------------------------------------------
__device__ __forceinline__ uint32_t smem_to_u32(const void* p) {
    uint32_t a;
    asm("{ .reg .u64 t; cvta.to.shared.u64 t, %1; cvt.u32.u64 %0, t; }" : "=r"(a) : "l"(p));
    return a;
}
#define CP16(dst, src) \
    asm volatile("cp.async.cg.shared.global [%0], [%1], 16;" :: "r"((uint32_t)(dst)), "l"(src) : "memory")
#define CP_COMMIT() asm volatile("cp.async.commit_group;" ::: "memory")
#define CP_WAIT(n)  asm volatile("cp.async.wait_group %0;" :: "n"(n) : "memory")
#define SWZ(b) ((b) ^ (((b) >> 3) & 0x70))
#define LDSM_X4(r0, r1, r2, r3, addr) \
    asm volatile("ldmatrix.sync.aligned.m8n8.x4.shared.b16 {%0,%1,%2,%3}, [%4];" \
                 : "=r"(r0), "=r"(r1), "=r"(r2), "=r"(r3) : "r"(addr))
#define MMA_F16(d, a, b0, b1) \
    asm volatile("mma.sync.aligned.m16n8k16.row.col.f32.f16.f16.f32 " \
                 "{%0,%1,%2,%3}, {%4,%5,%6,%7}, {%8,%9}, {%0,%1,%2,%3};" \
                 : "+f"((d)[0]), "+f"((d)[1]), "+f"((d)[2]), "+f"((d)[3]) \
                 : "r"((a)[0]), "r"((a)[1]), "r"((a)[2]), "r"((a)[3]), \
                   "r"(b0), "r"(b1))

// ---------------- setup kernels --------------------------------------------
__global__ void k_zero(float* out) {
    int i = blockIdx.x * blockDim.x + threadIdx.x;
    if (i < N_NODES) g_deg[i] = 0;
    if (i < N_BATCH) g_bcnt[i] = 0;
    if (i < N_BATCH * D_OUT) out[i] = 0.f;
}
__global__ void k_hist_deg(const int* __restrict__ dst) {
    int e = blockIdx.x * blockDim.x + threadIdx.x;
    if (e < N_EDGES) atomicAdd(&g_deg[dst[e]], 1);
}
__global__ void k_hist_batch(const int* __restrict__ batch) {
    int n = blockIdx.x * blockDim.x + threadIdx.x;
    if (n < N_NODES) atomicAdd(&g_bcnt[batch[n]], 1);
}
__global__ void k_scanA() {
    __shared__ int ws[32];
    int tid = threadIdx.x, lane = tid & 31, wid = tid >> 5;
    int i = blockIdx.x * 1024 + tid;
    int v = (i < N_NODES) ? g_deg[i] : 0;
    int x = v;
    #pragma unroll
    for (int o = 1; o < 32; o <<= 1) {
        int t = __shfl_up_sync(0xffffffffu, x, o);
        if (lane >= o) x += t;
    }
    if (lane == 31) ws[wid] = x;
    __syncthreads();
    if (wid == 0) {
        int y = ws[lane];
        #pragma unroll
        for (int o = 1; o < 32; o <<= 1) {
            int t = __shfl_up_sync(0xffffffffu, y, o);
            if (lane >= o) y += t;
        }
        ws[lane] = y;
    }
    __syncthreads();
    int incl = x + (wid ? ws[wid - 1] : 0);
    if (i < N_NODES) g_off[i] = incl - v;
    if (tid == 1023) g_bsum[blockIdx.x] = incl;
}
__global__ void k_scanB() {
    __shared__ int s[64];
    int tid = threadIdx.x;
    s[tid] = (tid < NB_SCAN) ? g_bsum[tid] : 0;
    __syncthreads();
    if (tid == 0) {
        int acc = 0;
        for (int i = 0; i < NB_SCAN; i++) { int t = s[i]; s[i] = acc; acc += t; }
        g_off[N_NODES] = acc;
    }
    __syncthreads();
    if (tid < NB_SCAN) g_bsum[tid] = s[tid];
}
__global__ void k_scanC() {
    int i = blockIdx.x * 1024 + threadIdx.x;
    if (i < N_NODES) {
        int o = g_off[i] + g_bsum[blockIdx.x];
        g_off[i] = o;
        g_cur[i] = o;
    }
}
__global__ void k_scatter(const int* __restrict__ src, const int* __restrict__ dst) {
    int e = blockIdx.x * blockDim.x + threadIdx.x;
    if (e < N_EDGES) {
        int p = atomicAdd(&g_cur[dst[e]], 1);
        g_ssrc[p] = src[e];
    }
}

// layer-1 combined weight (fp32): rows [0,15)=Wl1, [15,30)=Wr1, [30,32)=0
__global__ void k_buildW1(const float* __restrict__ Wl, const float* __restrict__ Wr) {
    int idx = blockIdx.x * blockDim.x + threadIdx.x;
    if (idx >= 32 * D_HID) return;
    int k = idx / D_HID, n = idx - k * D_HID;
    float v = 0.f;
    if (k < D_IN)          v = Wl[k * D_HID + n];
    else if (k < 2 * D_IN) v = Wr[(k - D_IN) * D_HID + n];
    g_W1[idx] = v;
}

// transposed fp16 weight: Wt[n][k], k<256:Wl, 256..511:Wr; row stride 512
__global__ void k_buildWt(const float* __restrict__ Wl, const float* __restrict__ Wr,
                          __half* __restrict__ Wt, int ncols) {
    int idx = blockIdx.x * blockDim.x + threadIdx.x;
    if (idx >= ncols * 512) return;
    int n = idx / 512, k = idx - n * 512;
    float v = (k < 256) ? Wl[k * ncols + n] : Wr[(k - 256) * ncols + n];
    Wt[n * 512 + k] = __float2half(v);
}

// ---------------- layer-1 concat build --------------------------------------
__global__ void k_agg15(const float* __restrict__ x, float* __restrict__ xc) {
    int warp = (blockIdx.x * blockDim.x + threadIdx.x) >> 5;
    if (warp >= N_NODES) return;
    int lane = threadIdx.x & 31;
    int s = g_off[warp], e = g_off[warp + 1];
    float acc = 0.f;
    for (int i = s; i < e; i++) {
        int sn = g_ssrc[i];
        if (lane < D_IN) acc += x[sn * D_IN + lane];
    }
    float inv = 1.f / (float)max(e - s, 1);
    float* row = xc + warp * 32;
    if (lane < D_IN) {
        row[lane] = acc * inv;
        row[D_IN + lane] = x[warp * D_IN + lane];
    }
    if (lane == 15) { row[30] = 0.f; row[31] = 0.f; }
}

// ---------------- mean aggregation: gather x-half fp16, fp32 mean, fp16 out --
__device__ __forceinline__ void acch(float* a, uint4 h) {
    const __half2* hp = (const __half2*)&h;
    #pragma unroll
    for (int p = 0; p < 4; p++) {
        float2 f = __half22float2(hp[p]);
        a[2 * p]     += f.x;
        a[2 * p + 1] += f.y;
    }
}
__global__ void k_aggmean(const __half* __restrict__ Ain, __half* __restrict__ Am) {
    int warp = (blockIdx.x * blockDim.x + threadIdx.x) >> 5;
    if (warp >= N_NODES) return;
    int lane = threadIdx.x & 31;
    int s = g_off[warp], e = g_off[warp + 1];
    float acc[8];
    #pragma unroll
    for (int j = 0; j < 8; j++) acc[j] = 0.f;
    int i = s;
    for (; i + 3 < e; i += 4) {
        int s0 = g_ssrc[i], s1 = g_ssrc[i + 1], s2 = g_ssrc[i + 2], s3 = g_ssrc[i + 3];
        uint4 v0 = *(const uint4*)(Ain + (size_t)s0 * 512 + 256 + lane * 8);
        uint4 v1 = *(const uint4*)(Ain + (size_t)s1 * 512 + 256 + lane * 8);
        uint4 v2 = *(const uint4*)(Ain + (size_t)s2 * 512 + 256 + lane * 8);
        uint4 v3 = *(const uint4*)(Ain + (size_t)s3 * 512 + 256 + lane * 8);
        acch(acc, v0); acch(acc, v1); acch(acc, v2); acch(acc, v3);
    }
    for (; i < e; i++) {
        int s0 = g_ssrc[i];
        uint4 v0 = *(const uint4*)(Ain + (size_t)s0 * 512 + 256 + lane * 8);
        acch(acc, v0);
    }
    float inv = 1.f / (float)max(e - s, 1);
    __half2 o[4];
    #pragma unroll
    for (int p = 0; p < 4; p++)
        o[p] = __floats2half2_rn(acc[2 * p] * inv, acc[2 * p + 1] * inv);
    *(uint4*)(Am + (size_t)warp * 512 + lane * 8) = *(uint4*)o;
}

// ---------------- layer-1 fused SIMT GEMM + LN + GELU ------------------------
__global__ __launch_bounds__(512)
void k_gemm1f(const float* __restrict__ xc, const float* __restrict__ W1,
              const float* __restrict__ bias, const float* __restrict__ gam,
              const float* __restrict__ bet, __half* __restrict__ Anext) {
    extern __shared__ float sm1[];
    float* As = sm1;               // [32][132]
    float* Ws = sm1 + 32 * 132;    // [32][256]
    int tid = threadIdx.x, lane = tid & 31, warp = tid >> 5;
    int row0 = blockIdx.x * 128;

    #pragma unroll
    for (int i = 0; i < 2; i++) {
        int t = tid + i * 512;
        int r = t >> 3, kq = (t & 7) * 4;
        float4 v = *(const float4*)&xc[(size_t)(row0 + r) * 32 + kq];
        As[(kq + 0) * 132 + r] = v.x; As[(kq + 1) * 132 + r] = v.y;
        As[(kq + 2) * 132 + r] = v.z; As[(kq + 3) * 132 + r] = v.w;
    }
    #pragma unroll
    for (int i = 0; i < 4; i++) {
        int t = tid + i * 512;
        int k = t >> 6, c4 = (t & 63) * 4;
        *(float4*)&Ws[k * 256 + c4] = *(const float4*)&W1[k * 256 + c4];
    }
    __syncthreads();

    float acc[8][8];
    #pragma unroll
    for (int r = 0; r < 8; r++)
        #pragma unroll
        for (int j = 0; j < 8; j++) acc[r][j] = 0.f;
    #pragma unroll 8
    for (int k = 0; k < 32; k++) {
        float a[8], b[8];
        #pragma unroll
        for (int r = 0; r < 8; r++) a[r] = As[k * 132 + warp * 8 + r];
        #pragma unroll
        for (int j = 0; j < 8; j++) b[j] = Ws[k * 256 + j * 32 + lane];
        #pragma unroll
        for (int r = 0; r < 8; r++)
            #pragma unroll
            for (int j = 0; j < 8; j++) acc[r][j] += a[r] * b[j];
    }
    #pragma unroll
    for (int j = 0; j < 8; j++) {
        float bj = bias[j * 32 + lane];
        #pragma unroll
        for (int r = 0; r < 8; r++) acc[r][j] += bj;
    }
    #pragma unroll
    for (int r = 0; r < 8; r++) {
        float s = 0.f, q = 0.f;
        #pragma unroll
        for (int j = 0; j < 8; j++) { s += acc[r][j]; q += acc[r][j] * acc[r][j]; }
        #pragma unroll
        for (int o = 16; o; o >>= 1) {
            s += __shfl_xor_sync(0xffffffffu, s, o);
            q += __shfl_xor_sync(0xffffffffu, q, o);
        }
        float mu = s * (1.f / 256.f);
        float var = fmaxf(q * (1.f / 256.f) - mu * mu, 0.f);
        float rs = rsqrtf(var + LN_EPS);
        int rg = row0 + warp * 8 + r;
        #pragma unroll
        for (int j = 0; j < 8; j++) {
            int c = j * 32 + lane;
            float y = (acc[r][j] - mu) * rs * gam[c] + bet[c];
            float o = y * normcdff(y);
            Anext[(size_t)rg * 512 + 256 + c] = __float2half(o);
        }
    }
}

// ---------------- fused fp16 tensor-core GEMM + bias + LN + GELU -------------
// K=512 (8 chunks of 64). BM=128, BN=NT, 512 threads (16 warps 4m x 4n)
// MODE 0: write x-half fp16 into Anext.  MODE 1: pool atomics into out.
template<int NT, int MODE>
__global__ __launch_bounds__(512)
void k_gemm_f(const __half* __restrict__ A, const __half* __restrict__ Wt,
              const float* __restrict__ bias, const float* __restrict__ gam,
              const float* __restrict__ bet, __half* __restrict__ Anext,
              float* __restrict__ out, const int* __restrict__ batch) {
    extern __shared__ char smem[];
    uint32_t sb = smem_to_u32(smem);
    constexpr int BBYTES = NT * 128;
    constexpr int STAGE = 16384 + BBYTES;
    constexpr int NB = NT / 32;
    constexpr int NB4 = NT / 64;
    constexpr int BAND = NT / 4;
    float2* red = (float2*)(smem + 2 * STAGE);   // [4 warp_n][128 rows]

    int tid = threadIdx.x, lane = tid & 31, warp = tid >> 5;
    int warp_m = warp & 3, warp_n = warp >> 2;
    int row0 = blockIdx.x * 128;

    float acc[2][NB][4];
    #pragma unroll
    for (int mi = 0; mi < 2; mi++)
        #pragma unroll
        for (int nb = 0; nb < NB; nb++)
            #pragma unroll
            for (int r = 0; r < 4; r++) acc[mi][nb][r] = 0.f;

    auto issue = [&](int c, int s) {
        uint32_t dA = sb + s * STAGE;
        uint32_t dB = dA + 16384;
        const __half* pa = A + (size_t)row0 * 512 + c * 64;
        const __half* pb = Wt + c * 64;
        #pragma unroll
        for (int i = 0; i < 2; i++) {
            int t = tid + i * 512;
            int r = t >> 3, seg = t & 7;
            CP16(dA + SWZ(r * 128 + seg * 16), pa + (size_t)r * 512 + seg * 8);
        }
        #pragma unroll
        for (int i = 0; i < NB4; i++) {
            int t = tid + i * 512;
            int r = t >> 3, seg = t & 7;
            CP16(dB + SWZ(r * 128 + seg * 16), pb + (size_t)r * 512 + seg * 8);
        }
        CP_COMMIT();
    };

    issue(0, 0);
    for (int c = 0; c < 8; c++) {
        int s = c & 1;
        if (c < 7) { issue(c + 1, s ^ 1); CP_WAIT(1); }
        else       { CP_WAIT(0); }
        __syncthreads();
        uint32_t sA = sb + s * STAGE, sB = sA + 16384;
        #pragma unroll
        for (int kk = 0; kk < 64; kk += 16) {
            uint32_t a[2][4], b[NB4][4];
            #pragma unroll
            for (int mi = 0; mi < 2; mi++) {
                int r = warp_m * 32 + mi * 16 + (lane & 15);
                int cb = (kk + (lane >> 4) * 8) * 2;
                LDSM_X4(a[mi][0], a[mi][1], a[mi][2], a[mi][3], sA + SWZ(r * 128 + cb));
            }
            #pragma unroll
            for (int nb4 = 0; nb4 < NB4; nb4++) {
                int g = lane >> 3;
                int n = warp_n * BAND + nb4 * 16 + (lane & 7) + (g >> 1) * 8;
                int kb = (kk + (g & 1) * 8) * 2;
                LDSM_X4(b[nb4][0], b[nb4][1], b[nb4][2], b[nb4][3], sB + SWZ(n * 128 + kb));
            }
            #pragma unroll
            for (int mi = 0; mi < 2; mi++)
                #pragma unroll
                for (int nb = 0; nb < NB; nb++) {
                    uint32_t b0 = b[nb >> 1][(nb & 1) * 2];
                    uint32_t b1 = b[nb >> 1][(nb & 1) * 2 + 1];
                    MMA_F16(acc[mi][nb], a[mi], b0, b1);
                }
        }
        __syncthreads();
    }

    int tr = lane >> 2, tc = lane & 3;
    #pragma unroll
    for (int nb = 0; nb < NB; nb++) {
        int cg = warp_n * BAND + nb * 8 + tc * 2;
        float bx = bias[cg], by = bias[cg + 1];
        #pragma unroll
        for (int mi = 0; mi < 2; mi++) {
            acc[mi][nb][0] += bx; acc[mi][nb][1] += by;
            acc[mi][nb][2] += bx; acc[mi][nb][3] += by;
        }
    }
    float ss[2][2], qq[2][2];
    #pragma unroll
    for (int mi = 0; mi < 2; mi++)
        #pragma unroll
        for (int h = 0; h < 2; h++) {
            float s = 0.f, q = 0.f;
            #pragma unroll
            for (int nb = 0; nb < NB; nb++) {
                float v0 = acc[mi][nb][2 * h], v1 = acc[mi][nb][2 * h + 1];
                s += v0 + v1; q += v0 * v0 + v1 * v1;
            }
            s += __shfl_xor_sync(0xffffffffu, s, 1);
            q += __shfl_xor_sync(0xffffffffu, q, 1);
            s += __shfl_xor_sync(0xffffffffu, s, 2);
            q += __shfl_xor_sync(0xffffffffu, q, 2);
            ss[mi][h] = s; qq[mi][h] = q;
        }
    if (tc == 0) {
        #pragma unroll
        for (int mi = 0; mi < 2; mi++)
            #pragma unroll
            for (int h = 0; h < 2; h++)
                red[warp_n * 128 + warp_m * 32 + mi * 16 + h * 8 + tr] =
                    make_float2(ss[mi][h], qq[mi][h]);
    }
    __syncthreads();
    float mean[2][2], rstd[2][2];
    #pragma unroll
    for (int mi = 0; mi < 2; mi++)
        #pragma unroll
        for (int h = 0; h < 2; h++) {
            int rloc = warp_m * 32 + mi * 16 + h * 8 + tr;
            float S = 0.f, Q = 0.f;
            #pragma unroll
            for (int wn = 0; wn < 4; wn++) {
                float2 p = red[wn * 128 + rloc];
                S += p.x; Q += p.y;
            }
            float mu = S * (1.f / NT);
            float var = fmaxf(Q * (1.f / NT) - mu * mu, 0.f);
            mean[mi][h] = mu;
            rstd[mi][h] = rsqrtf(var + LN_EPS);
        }
    #pragma unroll
    for (int nb = 0; nb < NB; nb++) {
        int cg = warp_n * BAND + nb * 8 + tc * 2;
        float g0 = gam[cg], g1 = gam[cg + 1];
        float t0 = bet[cg], t1 = bet[cg + 1];
        #pragma unroll
        for (int mi = 0; mi < 2; mi++)
            #pragma unroll
            for (int h = 0; h < 2; h++) {
                int rg = row0 + warp_m * 32 + mi * 16 + h * 8 + tr;
                float mu = mean[mi][h], rs = rstd[mi][h];
                float y0 = (acc[mi][nb][2 * h]     - mu) * rs * g0 + t0;
                float y1 = (acc[mi][nb][2 * h + 1] - mu) * rs * g1 + t1;
                float o0 = y0 * normcdff(y0);
                float o1 = y1 * normcdff(y1);
                if (MODE == 0) {
                    *(__half2*)(Anext + (size_t)rg * 512 + 256 + cg) = __floats2half2_rn(o0, o1);
                } else {
                    if (rg < N_NODES) {
                        int bidx = batch[rg];
                        atomicAdd(&out[bidx * D_OUT + cg],     o0);
                        atomicAdd(&out[bidx * D_OUT + cg + 1], o1);
                    }
                }
            }
    }
}

// ---------------- final division --------------------------------------------
__global__ void k_poolfin(float* __restrict__ out) {
    int i = blockIdx.x * blockDim.x + threadIdx.x;
    if (i < N_BATCH * D_OUT) {
        int c = g_bcnt[i / D_OUT];
        out[i] /= (float)max(c, 1);
    }
}

// ---------------- launch -----------------------------------------------------
extern "C" void kernel_launch(void* const* d_in, const int* in_sizes, int n_in,
                              void* d_out, int out_size) {
    const float* x     = (const float*)d_in[0];
    const int*   ei    = (const int*)d_in[1];
    const int*   src   = ei;
    const int*   dst   = ei + N_EDGES;
    const int*   batch = (const int*)d_in[2];
    const float* Wl1 = (const float*)d_in[3],  *Wr1 = (const float*)d_in[4];
    const float* b1  = (const float*)d_in[5],  *g1  = (const float*)d_in[6],  *bt1 = (const float*)d_in[7];
    const float* Wl2 = (const float*)d_in[8],  *Wr2 = (const float*)d_in[9];
    const float* b2  = (const float*)d_in[10], *g2  = (const float*)d_in[11], *bt2 = (const float*)d_in[12];
    const float* Wl3 = (const float*)d_in[13], *Wr3 = (const float*)d_in[14];
    const float* b3  = (const float*)d_in[15], *g3  = (const float*)d_in[16], *bt3 = (const float*)d_in[17];
    const float* Wl4 = (const float*)d_in[18], *Wr4 = (const float*)d_in[19];
    const float* b4  = (const float*)d_in[20], *g4  = (const float*)d_in[21], *bt4 = (const float*)d_in[22];
    float* out = (float*)d_out;

    float *xc1, *W1;
    __half *AA, *AB, *WtAll;
    cudaGetSymbolAddress((void**)&xc1,   g_xc1);
    cudaGetSymbolAddress((void**)&W1,    g_W1);
    cudaGetSymbolAddress((void**)&AA,    g_AA);
    cudaGetSymbolAddress((void**)&AB,    g_AB);
    cudaGetSymbolAddress((void**)&WtAll, g_WtAll);
    __half* Wt2 = WtAll;
    __half* Wt3 = WtAll + (size_t)256 * 512;
    __half* Wt4 = WtAll + (size_t)512 * 512;

    const int TB = 256;
    int gridE = (N_EDGES + TB - 1) / TB;
    int gridN = (N_NODES + TB - 1) / TB;
    int gridWarpN = (N_NODES * 32 + TB - 1) / TB;
    int gridTiles = N_PAD / 128;   // 391

    const int SM1   = (32 * 132 + 32 * 256) * 4;           // 49664
    const int SM256 = 2 * (16384 + 256 * 128) + 4096;      // 102400
    const int SM128 = 2 * (16384 + 128 * 128) + 4096;      // 69632
    cudaFuncSetAttribute(k_gemm1f, cudaFuncAttributeMaxDynamicSharedMemorySize, SM1);
    cudaFuncSetAttribute(k_gemm_f<256, 0>, cudaFuncAttributeMaxDynamicSharedMemorySize, SM256);
    cudaFuncSetAttribute(k_gemm_f<128, 1>, cudaFuncAttributeMaxDynamicSharedMemorySize, SM128);

    // ---- setup ----
    k_zero<<<gridN, TB>>>(out);
    k_hist_deg<<<gridE, TB>>>(dst);
    k_hist_batch<<<gridN, TB>>>(batch);
    k_scanA<<<NB_SCAN, 1024>>>();
    k_scanB<<<1, 64>>>();
    k_scanC<<<NB_SCAN, 1024>>>();
    k_scatter<<<gridE, TB>>>(src, dst);
    k_buildW1<<<(32 * D_HID + TB - 1) / TB, TB>>>(Wl1, Wr1);
    k_buildWt<<<(D_HID * 512 + TB - 1) / TB, TB>>>(Wl2, Wr2, Wt2, D_HID);
    k_buildWt<<<(D_HID * 512 + TB - 1) / TB, TB>>>(Wl3, Wr3, Wt3, D_HID);
    k_buildWt<<<(D_OUT * 512 + TB - 1) / TB, TB>>>(Wl4, Wr4, Wt4, D_OUT);

    // ---- layer 1: SIMT K=32 fused (writes x-half of AA) ----
    k_agg15<<<gridWarpN, TB>>>(x, xc1);
    k_gemm1f<<<gridTiles, 512, SM1>>>(xc1, W1, b1, g1, bt1, AA);

    // ---- layer 2 ----
    k_aggmean<<<gridWarpN, TB>>>(AA, AA);
    k_gemm_f<256, 0><<<gridTiles, 512, SM256>>>(AA, Wt2, b2, g2, bt2, AB, nullptr, nullptr);

    // ---- layer 3 ----
    k_aggmean<<<gridWarpN, TB>>>(AB, AB);
    k_gemm_f<256, 0><<<gridTiles, 512, SM256>>>(AB, Wt3, b3, g3, bt3, AA, nullptr, nullptr);

    // ---- layer 4: fused pool ----
    k_aggmean<<<gridWarpN, TB>>>(AA, AA);
    k_gemm_f<128, 1><<<gridTiles, 512, SM128>>>(AA, Wt4, b4, g4, bt4, nullptr, out, batch);

    k_poolfin<<<(N_BATCH * D_OUT + TB - 1) / TB, TB>>>(out);
}

// round 8
// speedup vs baseline: 1.7562x; 1.0566x over previous
#include <cuda_runtime.h>
#include <cuda_bf16.h>
#include <cuda_fp16.h>
#include <math.h>
#include <stdint.h>

#define N_NODES 50000
#define N_PAD   50048            // 391 * 128
#define N_EDGES 800000
#define N_BATCH 128
#define D_IN    15
#define D_HID   256
#define D_OUT   128
#define LN_EPS  1e-5f
#define NB_SCAN 49               // ceil(50000/1024)

// ---------------- device scratch -------------------------------------------
// Activation rows: 512 fp16 = [mean(0:256) | x(256:512)]
__device__ __half g_AA[(size_t)N_PAD * 512];          // 51 MB
__device__ __half g_AB[(size_t)N_PAD * 512];          // 51 MB
__device__ __half g_WtAll[(256 + 256 + 128) * 512];   // W^T fp16, layers 2,3,4
__device__ __half g_xc16[(size_t)N_PAD * 64];         // layer-1 fp16 concat (K=64, cols 30..63 = 0)
__device__ __half g_Wt1[256 * 64];                    // layer-1 W^T fp16
__device__ int   g_ssrc[N_EDGES];
__device__ int   g_off [N_NODES + 1];
__device__ int   g_cur [N_NODES];
__device__ int   g_deg [N_NODES];
__device__ int   g_bsum[64];
__device__ int   g_bcnt[N_BATCH];

// ---------------- PTX helpers ----------------------------------------------
__device__ __forceinline__ uint32_t smem_to_u32(const void* p) {
    uint32_t a;
    asm("{ .reg .u64 t; cvta.to.shared.u64 t, %1; cvt.u32.u64 %0, t; }" : "=r"(a) : "l"(p));
    return a;
}
#define CP16(dst, src) \
    asm volatile("cp.async.cg.shared.global [%0], [%1], 16;" :: "r"((uint32_t)(dst)), "l"(src) : "memory")
#define CP_COMMIT() asm volatile("cp.async.commit_group;" ::: "memory")
#define CP_WAIT(n)  asm volatile("cp.async.wait_group %0;" :: "n"(n) : "memory")
#define SWZ(b) ((b) ^ (((b) >> 3) & 0x70))
#define LDSM_X4(r0, r1, r2, r3, addr) \
    asm volatile("ldmatrix.sync.aligned.m8n8.x4.shared.b16 {%0,%1,%2,%3}, [%4];" \
                 : "=r"(r0), "=r"(r1), "=r"(r2), "=r"(r3) : "r"(addr))
#define MMA_F16(d, a, b0, b1) \
    asm volatile("mma.sync.aligned.m16n8k16.row.col.f32.f16.f16.f32 " \
                 "{%0,%1,%2,%3}, {%4,%5,%6,%7}, {%8,%9}, {%0,%1,%2,%3};" \
                 : "+f"((d)[0]), "+f"((d)[1]), "+f"((d)[2]), "+f"((d)[3]) \
                 : "r"((a)[0]), "r"((a)[1]), "r"((a)[2]), "r"((a)[3]), \
                   "r"(b0), "r"(b1))

// ---------------- setup kernels --------------------------------------------
__global__ void k_zero(float* out) {
    int i = blockIdx.x * blockDim.x + threadIdx.x;
    if (i < N_NODES) g_deg[i] = 0;
    if (i < N_BATCH) g_bcnt[i] = 0;
    if (i < N_BATCH * D_OUT) out[i] = 0.f;
}
__global__ void k_hist_deg(const int* __restrict__ dst) {
    int e = blockIdx.x * blockDim.x + threadIdx.x;
    if (e < N_EDGES) atomicAdd(&g_deg[dst[e]], 1);
}
__global__ void k_hist_batch(const int* __restrict__ batch) {
    int n = blockIdx.x * blockDim.x + threadIdx.x;
    if (n < N_NODES) atomicAdd(&g_bcnt[batch[n]], 1);
}
__global__ void k_scanA() {
    __shared__ int ws[32];
    int tid = threadIdx.x, lane = tid & 31, wid = tid >> 5;
    int i = blockIdx.x * 1024 + tid;
    int v = (i < N_NODES) ? g_deg[i] : 0;
    int x = v;
    #pragma unroll
    for (int o = 1; o < 32; o <<= 1) {
        int t = __shfl_up_sync(0xffffffffu, x, o);
        if (lane >= o) x += t;
    }
    if (lane == 31) ws[wid] = x;
    __syncthreads();
    if (wid == 0) {
        int y = ws[lane];
        #pragma unroll
        for (int o = 1; o < 32; o <<= 1) {
            int t = __shfl_up_sync(0xffffffffu, y, o);
            if (lane >= o) y += t;
        }
        ws[lane] = y;
    }
    __syncthreads();
    int incl = x + (wid ? ws[wid - 1] : 0);
    if (i < N_NODES) g_off[i] = incl - v;
    if (tid == 1023) g_bsum[blockIdx.x] = incl;
}
__global__ void k_scanB() {
    __shared__ int s[64];
    int tid = threadIdx.x;
    s[tid] = (tid < NB_SCAN) ? g_bsum[tid] : 0;
    __syncthreads();
    if (tid == 0) {
        int acc = 0;
        for (int i = 0; i < NB_SCAN; i++) { int t = s[i]; s[i] = acc; acc += t; }
        g_off[N_NODES] = acc;
    }
    __syncthreads();
    if (tid < NB_SCAN) g_bsum[tid] = s[tid];
}
__global__ void k_scanC() {
    int i = blockIdx.x * 1024 + threadIdx.x;
    if (i < N_NODES) {
        int o = g_off[i] + g_bsum[blockIdx.x];
        g_off[i] = o;
        g_cur[i] = o;
    }
}
__global__ void k_scatter(const int* __restrict__ src, const int* __restrict__ dst) {
    int e = blockIdx.x * blockDim.x + threadIdx.x;
    if (e < N_EDGES) {
        int p = atomicAdd(&g_cur[dst[e]], 1);
        g_ssrc[p] = src[e];
    }
}

// layer-1 transposed fp16 weight: Wt1[n][k], k<15:Wl1[k][n], 15..29:Wr1[k-15][n], else 0
__global__ void k_buildWt1(const float* __restrict__ Wl, const float* __restrict__ Wr) {
    int idx = blockIdx.x * blockDim.x + threadIdx.x;
    if (idx >= 256 * 64) return;
    int n = idx >> 6, k = idx & 63;
    float v = 0.f;
    if (k < D_IN)          v = Wl[k * D_HID + n];
    else if (k < 2 * D_IN) v = Wr[(k - D_IN) * D_HID + n];
    g_Wt1[idx] = __float2half(v);
}

// transposed fp16 weight: Wt[n][k], k<256:Wl, 256..511:Wr; row stride 512
__global__ void k_buildWt(const float* __restrict__ Wl, const float* __restrict__ Wr,
                          __half* __restrict__ Wt, int ncols) {
    int idx = blockIdx.x * blockDim.x + threadIdx.x;
    if (idx >= ncols * 512) return;
    int n = idx / 512, k = idx - n * 512;
    float v = (k < 256) ? Wl[k * ncols + n] : Wr[(k - 256) * ncols + n];
    Wt[n * 512 + k] = __float2half(v);
}

// ---------------- layer-1 concat build (fp16, K=64 padded) -------------------
__global__ void k_agg15h(const float* __restrict__ x, __half* __restrict__ xc) {
    int warp = (blockIdx.x * blockDim.x + threadIdx.x) >> 5;
    if (warp >= N_NODES) return;
    int lane = threadIdx.x & 31;
    int s = g_off[warp], e = g_off[warp + 1];
    float acc = 0.f;
    for (int i = s; i < e; i++) {
        int sn = g_ssrc[i];
        if (lane < D_IN) acc += x[sn * D_IN + lane];
    }
    float inv = 1.f / (float)max(e - s, 1);
    __half* row = xc + (size_t)warp * 64;
    if (lane < D_IN) {
        row[lane]        = __float2half(acc * inv);
        row[D_IN + lane] = __float2half(x[warp * D_IN + lane]);
    }
    // cols 30..63 and pad rows stay zero (zero-initialized globals, never written)
}

// ---------------- mean aggregation: gather x-half fp16, fp32 mean, fp16 out --
__device__ __forceinline__ void acch(float* a, uint4 h) {
    const __half2* hp = (const __half2*)&h;
    #pragma unroll
    for (int p = 0; p < 4; p++) {
        float2 f = __half22float2(hp[p]);
        a[2 * p]     += f.x;
        a[2 * p + 1] += f.y;
    }
}
__global__ void k_aggmean(const __half* __restrict__ Ain, __half* __restrict__ Am) {
    int warp = (blockIdx.x * blockDim.x + threadIdx.x) >> 5;
    if (warp >= N_NODES) return;
    int lane = threadIdx.x & 31;
    int s = g_off[warp], e = g_off[warp + 1];
    float acc[8];
    #pragma unroll
    for (int j = 0; j < 8; j++) acc[j] = 0.f;
    int i = s;
    // 8-way unroll: 8 independent 16B loads in flight per warp
    for (; i + 7 < e; i += 8) {
        uint4 v[8];
        #pragma unroll
        for (int u = 0; u < 8; u++) {
            int sn = g_ssrc[i + u];
            v[u] = *(const uint4*)(Ain + (size_t)sn * 512 + 256 + lane * 8);
        }
        #pragma unroll
        for (int u = 0; u < 8; u++) acch(acc, v[u]);
    }
    for (; i + 3 < e; i += 4) {
        uint4 v[4];
        #pragma unroll
        for (int u = 0; u < 4; u++) {
            int sn = g_ssrc[i + u];
            v[u] = *(const uint4*)(Ain + (size_t)sn * 512 + 256 + lane * 8);
        }
        #pragma unroll
        for (int u = 0; u < 4; u++) acch(acc, v[u]);
    }
    for (; i < e; i++) {
        int sn = g_ssrc[i];
        uint4 v = *(const uint4*)(Ain + (size_t)sn * 512 + 256 + lane * 8);
        acch(acc, v);
    }
    float inv = 1.f / (float)max(e - s, 1);
    __half2 o[4];
    #pragma unroll
    for (int p = 0; p < 4; p++)
        o[p] = __floats2half2_rn(acc[2 * p] * inv, acc[2 * p + 1] * inv);
    *(uint4*)(Am + (size_t)warp * 512 + lane * 8) = *(uint4*)o;
}

// ---------------- fused fp16 tensor-core GEMM + bias + LN + GELU -------------
// K = NC*64.  BM=128, BN=NT, 512 threads (16 warps 4m x 4n)
// A row stride = K halves; Wt row stride = K halves.
// MODE 0: write x-half fp16 into Anext (row stride 512).  MODE 1: pool atomics.
template<int NT, int MODE, int NC>
__global__ __launch_bounds__(512)
void k_gemm_f(const __half* __restrict__ A, const __half* __restrict__ Wt,
              const float* __restrict__ bias, const float* __restrict__ gam,
              const float* __restrict__ bet, __half* __restrict__ Anext,
              float* __restrict__ out, const int* __restrict__ batch) {
    extern __shared__ char smem[];
    uint32_t sb = smem_to_u32(smem);
    constexpr int K = NC * 64;
    constexpr int BBYTES = NT * 128;
    constexpr int STAGE = 16384 + BBYTES;
    constexpr int NB = NT / 32;
    constexpr int NB4 = NT / 64;
    constexpr int BAND = NT / 4;
    float2* red = (float2*)(smem + 2 * STAGE);   // [4 warp_n][128 rows]

    int tid = threadIdx.x, lane = tid & 31, warp = tid >> 5;
    int warp_m = warp & 3, warp_n = warp >> 2;
    int row0 = blockIdx.x * 128;

    float acc[2][NB][4];
    #pragma unroll
    for (int mi = 0; mi < 2; mi++)
        #pragma unroll
        for (int nb = 0; nb < NB; nb++)
            #pragma unroll
            for (int r = 0; r < 4; r++) acc[mi][nb][r] = 0.f;

    auto issue = [&](int c, int s) {
        uint32_t dA = sb + s * STAGE;
        uint32_t dB = dA + 16384;
        const __half* pa = A + (size_t)row0 * K + c * 64;
        const __half* pb = Wt + c * 64;
        #pragma unroll
        for (int i = 0; i < 2; i++) {
            int t = tid + i * 512;
            int r = t >> 3, seg = t & 7;
            CP16(dA + SWZ(r * 128 + seg * 16), pa + (size_t)r * K + seg * 8);
        }
        #pragma unroll
        for (int i = 0; i < NB4; i++) {
            int t = tid + i * 512;
            int r = t >> 3, seg = t & 7;
            CP16(dB + SWZ(r * 128 + seg * 16), pb + (size_t)r * K + seg * 8);
        }
        CP_COMMIT();
    };

    issue(0, 0);
    for (int c = 0; c < NC; c++) {
        int s = c & 1;
        if (c < NC - 1) { issue(c + 1, s ^ 1); CP_WAIT(1); }
        else            { CP_WAIT(0); }
        __syncthreads();
        uint32_t sA = sb + s * STAGE, sB = sA + 16384;
        #pragma unroll
        for (int kk = 0; kk < 64; kk += 16) {
            uint32_t a[2][4], b[NB4][4];
            #pragma unroll
            for (int mi = 0; mi < 2; mi++) {
                int r = warp_m * 32 + mi * 16 + (lane & 15);
                int cb = (kk + (lane >> 4) * 8) * 2;
                LDSM_X4(a[mi][0], a[mi][1], a[mi][2], a[mi][3], sA + SWZ(r * 128 + cb));
            }
            #pragma unroll
            for (int nb4 = 0; nb4 < NB4; nb4++) {
                int g = lane >> 3;
                int n = warp_n * BAND + nb4 * 16 + (lane & 7) + (g >> 1) * 8;
                int kb = (kk + (g & 1) * 8) * 2;
                LDSM_X4(b[nb4][0], b[nb4][1], b[nb4][2], b[nb4][3], sB + SWZ(n * 128 + kb));
            }
            #pragma unroll
            for (int mi = 0; mi < 2; mi++)
                #pragma unroll
                for (int nb = 0; nb < NB; nb++) {
                    uint32_t b0 = b[nb >> 1][(nb & 1) * 2];
                    uint32_t b1 = b[nb >> 1][(nb & 1) * 2 + 1];
                    MMA_F16(acc[mi][nb], a[mi], b0, b1);
                }
        }
        __syncthreads();
    }

    int tr = lane >> 2, tc = lane & 3;
    #pragma unroll
    for (int nb = 0; nb < NB; nb++) {
        int cg = warp_n * BAND + nb * 8 + tc * 2;
        float bx = bias[cg], by = bias[cg + 1];
        #pragma unroll
        for (int mi = 0; mi < 2; mi++) {
            acc[mi][nb][0] += bx; acc[mi][nb][1] += by;
            acc[mi][nb][2] += bx; acc[mi][nb][3] += by;
        }
    }
    float ss[2][2], qq[2][2];
    #pragma unroll
    for (int mi = 0; mi < 2; mi++)
        #pragma unroll
        for (int h = 0; h < 2; h++) {
            float s = 0.f, q = 0.f;
            #pragma unroll
            for (int nb = 0; nb < NB; nb++) {
                float v0 = acc[mi][nb][2 * h], v1 = acc[mi][nb][2 * h + 1];
                s += v0 + v1; q += v0 * v0 + v1 * v1;
            }
            s += __shfl_xor_sync(0xffffffffu, s, 1);
            q += __shfl_xor_sync(0xffffffffu, q, 1);
            s += __shfl_xor_sync(0xffffffffu, s, 2);
            q += __shfl_xor_sync(0xffffffffu, q, 2);
            ss[mi][h] = s; qq[mi][h] = q;
        }
    if (tc == 0) {
        #pragma unroll
        for (int mi = 0; mi < 2; mi++)
            #pragma unroll
            for (int h = 0; h < 2; h++)
                red[warp_n * 128 + warp_m * 32 + mi * 16 + h * 8 + tr] =
                    make_float2(ss[mi][h], qq[mi][h]);
    }
    __syncthreads();
    float mean[2][2], rstd[2][2];
    #pragma unroll
    for (int mi = 0; mi < 2; mi++)
        #pragma unroll
        for (int h = 0; h < 2; h++) {
            int rloc = warp_m * 32 + mi * 16 + h * 8 + tr;
            float S = 0.f, Q = 0.f;
            #pragma unroll
            for (int wn = 0; wn < 4; wn++) {
                float2 p = red[wn * 128 + rloc];
                S += p.x; Q += p.y;
            }
            float mu = S * (1.f / NT);
            float var = fmaxf(Q * (1.f / NT) - mu * mu, 0.f);
            mean[mi][h] = mu;
            rstd[mi][h] = rsqrtf(var + LN_EPS);
        }
    #pragma unroll
    for (int nb = 0; nb < NB; nb++) {
        int cg = warp_n * BAND + nb * 8 + tc * 2;
        float g0 = gam[cg], g1 = gam[cg + 1];
        float t0 = bet[cg], t1 = bet[cg + 1];
        #pragma unroll
        for (int mi = 0; mi < 2; mi++)
            #pragma unroll
            for (int h = 0; h < 2; h++) {
                int rg = row0 + warp_m * 32 + mi * 16 + h * 8 + tr;
                float mu = mean[mi][h], rs = rstd[mi][h];
                float y0 = (acc[mi][nb][2 * h]     - mu) * rs * g0 + t0;
                float y1 = (acc[mi][nb][2 * h + 1] - mu) * rs * g1 + t1;
                float o0 = y0 * normcdff(y0);
                float o1 = y1 * normcdff(y1);
                if (MODE == 0) {
                    *(__half2*)(Anext + (size_t)rg * 512 + 256 + cg) = __floats2half2_rn(o0, o1);
                } else {
                    if (rg < N_NODES) {
                        int bidx = batch[rg];
                        atomicAdd(&out[bidx * D_OUT + cg],     o0);
                        atomicAdd(&out[bidx * D_OUT + cg + 1], o1);
                    }
                }
            }
    }
}

// ---------------- final division --------------------------------------------
__global__ void k_poolfin(float* __restrict__ out) {
    int i = blockIdx.x * blockDim.x + threadIdx.x;
    if (i < N_BATCH * D_OUT) {
        int c = g_bcnt[i / D_OUT];
        out[i] /= (float)max(c, 1);
    }
}

// ---------------- launch -----------------------------------------------------
extern "C" void kernel_launch(void* const* d_in, const int* in_sizes, int n_in,
                              void* d_out, int out_size) {
    const float* x     = (const float*)d_in[0];
    const int*   ei    = (const int*)d_in[1];
    const int*   src   = ei;
    const int*   dst   = ei + N_EDGES;
    const int*   batch = (const int*)d_in[2];
    const float* Wl1 = (const float*)d_in[3],  *Wr1 = (const float*)d_in[4];
    const float* b1  = (const float*)d_in[5],  *g1  = (const float*)d_in[6],  *bt1 = (const float*)d_in[7];
    const float* Wl2 = (const float*)d_in[8],  *Wr2 = (const float*)d_in[9];
    const float* b2  = (const float*)d_in[10], *g2  = (const float*)d_in[11], *bt2 = (const float*)d_in[12];
    const float* Wl3 = (const float*)d_in[13], *Wr3 = (const float*)d_in[14];
    const float* b3  = (const float*)d_in[15], *g3  = (const float*)d_in[16], *bt3 = (const float*)d_in[17];
    const float* Wl4 = (const float*)d_in[18], *Wr4 = (const float*)d_in[19];
    const float* b4  = (const float*)d_in[20], *g4  = (const float*)d_in[21], *bt4 = (const float*)d_in[22];
    float* out = (float*)d_out;

    __half *AA, *AB, *WtAll, *xc16, *Wt1;
    cudaGetSymbolAddress((void**)&AA,    g_AA);
    cudaGetSymbolAddress((void**)&AB,    g_AB);
    cudaGetSymbolAddress((void**)&WtAll, g_WtAll);
    cudaGetSymbolAddress((void**)&xc16,  g_xc16);
    cudaGetSymbolAddress((void**)&Wt1,   g_Wt1);
    __half* Wt2 = WtAll;
    __half* Wt3 = WtAll + (size_t)256 * 512;
    __half* Wt4 = WtAll + (size_t)512 * 512;

    const int TB = 256;
    int gridE = (N_EDGES + TB - 1) / TB;
    int gridN = (N_NODES + TB - 1) / TB;
    int gridWarpN = (N_NODES * 32 + TB - 1) / TB;
    int gridTiles = N_PAD / 128;   // 391

    const int SM256 = 2 * (16384 + 256 * 128) + 4096;      // 102400
    const int SM128 = 2 * (16384 + 128 * 128) + 4096;      // 69632
    cudaFuncSetAttribute(k_gemm_f<256, 0, 8>, cudaFuncAttributeMaxDynamicSharedMemorySize, SM256);
    cudaFuncSetAttribute(k_gemm_f<256, 0, 1>, cudaFuncAttributeMaxDynamicSharedMemorySize, SM256);
    cudaFuncSetAttribute(k_gemm_f<128, 1, 8>, cudaFuncAttributeMaxDynamicSharedMemorySize, SM128);

    // ---- setup ----
    k_zero<<<gridN, TB>>>(out);
    k_hist_deg<<<gridE, TB>>>(dst);
    k_hist_batch<<<gridN, TB>>>(batch);
    k_scanA<<<NB_SCAN, 1024>>>();
    k_scanB<<<1, 64>>>();
    k_scanC<<<NB_SCAN, 1024>>>();
    k_scatter<<<gridE, TB>>>(src, dst);
    k_buildWt1<<<(256 * 64 + TB - 1) / TB, TB>>>(Wl1, Wr1);
    k_buildWt<<<(D_HID * 512 + TB - 1) / TB, TB>>>(Wl2, Wr2, Wt2, D_HID);
    k_buildWt<<<(D_HID * 512 + TB - 1) / TB, TB>>>(Wl3, Wr3, Wt3, D_HID);
    k_buildWt<<<(D_OUT * 512 + TB - 1) / TB, TB>>>(Wl4, Wr4, Wt4, D_OUT);

    // ---- layer 1: tensor-core K=64 fused (writes x-half of AA) ----
    k_agg15h<<<gridWarpN, TB>>>(x, xc16);
    k_gemm_f<256, 0, 1><<<gridTiles, 512, SM256>>>(xc16, Wt1, b1, g1, bt1, AA, nullptr, nullptr);

    // ---- layer 2 ----
    k_aggmean<<<gridWarpN, TB>>>(AA, AA);
    k_gemm_f<256, 0, 8><<<gridTiles, 512, SM256>>>(AA, Wt2, b2, g2, bt2, AB, nullptr, nullptr);

    // ---- layer 3 ----
    k_aggmean<<<gridWarpN, TB>>>(AB, AB);
    k_gemm_f<256, 0, 8><<<gridTiles, 512, SM256>>>(AB, Wt3, b3, g3, bt3, AA, nullptr, nullptr);

    // ---- layer 4: fused pool ----
    k_aggmean<<<gridWarpN, TB>>>(AA, AA);
    k_gemm_f<128, 1, 8><<<gridTiles, 512, SM128>>>(AA, Wt4, b4, g4, bt4, nullptr, out, batch);

    k_poolfin<<<(N_BATCH * D_OUT + TB - 1) / TB, TB>>>(out);
}